// round 5
// baseline (speedup 1.0000x reference)
#include <cuda_runtime.h>
#include <math.h>

// ---------------------------------------------------------------------------
// Problem constants
// ---------------------------------------------------------------------------
#define B_DIM   4096
#define N_DIM   180
#define NV2     4096
#define IN_DIM  542            // 3*N + 2
#define KTOT    4640           // IN_DIM + NV2 padded to multiple of 16
#define K2      4096
#define N2PAD   384            // 180 + 180 + 1 padded to multiple of 128

// Output layout (tuple flattened in return order, all fp32)
#define OFF_MU  0
#define OFF_PI  737280
#define OFF_FB  741376
#define OFF_V   1478656
#define OFF_Z   18255872
#define OFF_X   35033088
#define OFF_B   51810304

#define BETA_MEM   0.95122942450071400910f   // exp(-1/20)
#define RHO_AD     0.99501247919268232265f   // exp(-1/200)
#define ONE_M_RHO  0.00498752080731767735f
#define BETA_AD    1.8f
#define ALPHA_F    0.9f

#define TAU_BORDER 1e-4f       // |v - B_thresh| band that triggers fp64 refinement
#define MAXB       65536       // capacity of borderline list

// ---------------------------------------------------------------------------
// Scratch (static device globals -- no runtime allocation allowed)
// ---------------------------------------------------------------------------
__device__ float g_A[(size_t)B_DIM * KTOT];   // [B, 4640]  packed activations
__device__ float g_W[(size_t)NV2 * KTOT];     // [NV2, 4640] packed weights
__device__ float g_W2[(size_t)N2PAD * K2];    // [384, 4096] packed stage-2 weights
__device__ float g_b2[N2PAD];
__device__ int   g_cnt;                        // borderline counter
__device__ int2  g_list[MAXB];                 // borderline (row, col) list

// ---------------------------------------------------------------------------
// f32x2 packed-FMA helpers (FFMA2 path; only reachable via inline PTX)
// ---------------------------------------------------------------------------
__device__ __forceinline__ unsigned long long pack_dup(float x) {
    unsigned long long r;
    asm("mov.b64 %0, {%1, %1};" : "=l"(r) : "f"(x));
    return r;
}
__device__ __forceinline__ void ffma2(unsigned long long& d,
                                      unsigned long long a,
                                      unsigned long long b) {
    asm("fma.rn.f32x2 %0, %1, %2, %0;" : "+l"(d) : "l"(a), "l"(b));
}
__device__ __forceinline__ float2 unpack2(unsigned long long v) {
    float2 r;
    asm("mov.b64 {%0, %1}, %2;" : "=f"(r.x), "=f"(r.y) : "l"(v));
    return r;
}

// ---------------------------------------------------------------------------
// Reset + pack kernels
// ---------------------------------------------------------------------------
__global__ void reset_kernel() { g_cnt = 0; }

__global__ void pack_A_kernel(const float* __restrict__ x_l4,
                              const float* __restrict__ x_l23,
                              const float* __restrict__ cue,
                              const float* __restrict__ task,
                              const float* __restrict__ x_prev) {
    int b = blockIdx.y;
    int k = blockIdx.x * blockDim.x + threadIdx.x;
    if (k >= KTOT) return;
    float v;
    if (k < N_DIM)                 v = x_l4[b * N_DIM + k];
    else if (k < 2 * N_DIM)        v = x_l23[b * N_DIM + (k - N_DIM)];
    else if (k < 3 * N_DIM)        v = cue[b * N_DIM + (k - 2 * N_DIM)];
    else if (k < IN_DIM)           v = task[b * 2 + (k - 3 * N_DIM)];
    else if (k < IN_DIM + NV2)     v = x_prev[(size_t)b * NV2 + (k - IN_DIM)];
    else                           v = 0.0f;
    g_A[(size_t)b * KTOT + k] = v;
}

__global__ void pack_W_kernel(const float* __restrict__ W_in,
                              const float* __restrict__ W_rec) {
    int n = blockIdx.y;
    int k = blockIdx.x * blockDim.x + threadIdx.x;
    if (k >= KTOT) return;
    float v;
    if (k < IN_DIM)                v = W_in[(size_t)n * IN_DIM + k];
    else if (k < IN_DIM + NV2)     v = W_rec[(size_t)n * NV2 + (k - IN_DIM)];
    else                           v = 0.0f;
    g_W[(size_t)n * KTOT + k] = v;
}

__global__ void pack_W2_kernel(const float* __restrict__ W_mu, const float* __restrict__ b_mu,
                               const float* __restrict__ W_fb, const float* __restrict__ b_fb,
                               const float* __restrict__ W_pi, const float* __restrict__ b_pi) {
    int r = blockIdx.y;
    int k = blockIdx.x * blockDim.x + threadIdx.x;
    if (k >= K2) return;
    float v = 0.0f;
    if (r < N_DIM)            v = W_mu[(size_t)r * K2 + k];
    else if (r < 2 * N_DIM)   v = W_fb[(size_t)(r - N_DIM) * K2 + k];
    else if (r == 2 * N_DIM)  v = W_pi[k];
    g_W2[(size_t)r * K2 + k] = v;
    if (k == 0) {
        float bb = 0.0f;
        if (r < N_DIM)           bb = b_mu[r];
        else if (r < 2 * N_DIM)  bb = b_fb[r - N_DIM];
        else if (r == 2 * N_DIM) bb = b_pi[0];
        g_b2[r] = bb;
    }
}

// ---------------------------------------------------------------------------
// GEMM 1: drive = g_A @ g_W^T + b_in, fused spiking epilogue + borderline flag
//   128x128 tile, BK=16, 256 threads, 8x8/thread via FFMA2
// ---------------------------------------------------------------------------
#define BM 128
#define BN 128
#define BK 16
#define LDS_S 132           // padded row stride (mult of 4 for vector LDS)
#define NKT (KTOT / BK)     // 290

__device__ __forceinline__ void stash128(float (*S)[LDS_S], int lrow, int lcol,
                                         float4 r0, float4 r1) {
    S[lcol + 0][lrow] = r0.x; S[lcol + 1][lrow] = r0.y;
    S[lcol + 2][lrow] = r0.z; S[lcol + 3][lrow] = r0.w;
    S[lcol + 0][lrow + 64] = r1.x; S[lcol + 1][lrow + 64] = r1.y;
    S[lcol + 2][lrow + 64] = r1.z; S[lcol + 3][lrow + 64] = r1.w;
}

__global__ __launch_bounds__(256)
void gemm1_kernel(const float* __restrict__ v_prev, const float* __restrict__ z_prev,
                  const float* __restrict__ x_prev, const float* __restrict__ b_prev,
                  const float* __restrict__ adapt_mask, const float* __restrict__ b_in,
                  float* __restrict__ out) {
    __shared__ __align__(16) float As[2][BK][LDS_S];
    __shared__ __align__(16) float Bs[2][BK][LDS_S];

    const int tid = threadIdx.x;
    const int tx = tid & 15;          // 0..15 -> 8 output cols each
    const int ty = tid >> 4;          // 0..15 -> 8 output rows each
    const int bm = blockIdx.y, bn = blockIdx.x;

    const int lrow = tid >> 2;        // 0..63
    const int lcol = (tid & 3) << 2;  // 0,4,8,12

    const float* Ag = g_A + (size_t)(bm * BM + lrow) * KTOT + lcol;
    const float* Wg = g_W + (size_t)(bn * BN + lrow) * KTOT + lcol;
    const size_t rstep = (size_t)64 * KTOT;

    unsigned long long acc[8][4];
#pragma unroll
    for (int i = 0; i < 8; i++)
#pragma unroll
        for (int j = 0; j < 4; j++) acc[i][j] = 0ull;

    // prologue: tile 0
    float4 ra0 = *(const float4*)(Ag);
    float4 ra1 = *(const float4*)(Ag + rstep);
    float4 rb0 = *(const float4*)(Wg);
    float4 rb1 = *(const float4*)(Wg + rstep);
    stash128(As[0], lrow, lcol, ra0, ra1);
    stash128(Bs[0], lrow, lcol, rb0, rb1);
    __syncthreads();

    int buf = 0;
    for (int kt = 0; kt < NKT; kt++) {
        if (kt + 1 < NKT) {
            const float* Ap = Ag + (size_t)(kt + 1) * BK;
            const float* Wp = Wg + (size_t)(kt + 1) * BK;
            ra0 = *(const float4*)(Ap);
            ra1 = *(const float4*)(Ap + rstep);
            rb0 = *(const float4*)(Wp);
            rb1 = *(const float4*)(Wp + rstep);
        }
#pragma unroll
        for (int kk = 0; kk < BK; kk++) {
            float4 a0 = *(const float4*)&As[buf][kk][ty * 8];
            float4 a1 = *(const float4*)&As[buf][kk][ty * 8 + 4];
            ulonglong2 b01 = *(const ulonglong2*)&Bs[buf][kk][tx * 8];
            ulonglong2 b23 = *(const ulonglong2*)&Bs[buf][kk][tx * 8 + 4];
            unsigned long long ad[8];
            ad[0] = pack_dup(a0.x); ad[1] = pack_dup(a0.y);
            ad[2] = pack_dup(a0.z); ad[3] = pack_dup(a0.w);
            ad[4] = pack_dup(a1.x); ad[5] = pack_dup(a1.y);
            ad[6] = pack_dup(a1.z); ad[7] = pack_dup(a1.w);
#pragma unroll
            for (int i = 0; i < 8; i++) {
                ffma2(acc[i][0], ad[i], b01.x);
                ffma2(acc[i][1], ad[i], b01.y);
                ffma2(acc[i][2], ad[i], b23.x);
                ffma2(acc[i][3], ad[i], b23.y);
            }
        }
        __syncthreads();
        if (kt + 1 < NKT) {
            int nb = buf ^ 1;
            stash128(As[nb], lrow, lcol, ra0, ra1);
            stash128(Bs[nb], lrow, lcol, rb0, rb1);
            __syncthreads();
            buf = nb;
        }
    }

    // --- fused spiking epilogue ---
    const int row0 = bm * BM + ty * 8;
    const int col0 = bn * BN + tx * 8;
    float am[8], bi[8];
    *(float4*)&am[0] = *(const float4*)(adapt_mask + col0);
    *(float4*)&am[4] = *(const float4*)(adapt_mask + col0 + 4);
    *(float4*)&bi[0] = *(const float4*)(b_in + col0);
    *(float4*)&bi[4] = *(const float4*)(b_in + col0 + 4);

#pragma unroll
    for (int i = 0; i < 8; i++) {
        const size_t base = (size_t)(row0 + i) * NV2 + col0;
        float vp[8], zp[8], bp[8], xp[8];
        *(float4*)&vp[0] = *(const float4*)(v_prev + base);
        *(float4*)&vp[4] = *(const float4*)(v_prev + base + 4);
        *(float4*)&zp[0] = *(const float4*)(z_prev + base);
        *(float4*)&zp[4] = *(const float4*)(z_prev + base + 4);
        *(float4*)&bp[0] = *(const float4*)(b_prev + base);
        *(float4*)&bp[4] = *(const float4*)(b_prev + base + 4);
        *(float4*)&xp[0] = *(const float4*)(x_prev + base);
        *(float4*)&xp[4] = *(const float4*)(x_prev + base + 4);

        float dr[8];
#pragma unroll
        for (int p = 0; p < 4; p++) {
            float2 d = unpack2(acc[i][p]);
            dr[p * 2] = d.x; dr[p * 2 + 1] = d.y;
        }
        float vo[8], zo[8], xo[8], bo[8];
#pragma unroll
        for (int j = 0; j < 8; j++) {
            float drive = dr[j] + bi[j];
            float v = BETA_MEM * vp[j] + drive - zp[j];       // V_THRESH = 1
            float Bth = fmaf(BETA_AD, bp[j], 1.0f);
            float u = v - Bth;
            float z = u > 0.0f ? 1.0f : 0.0f;
            if (fabsf(u) < TAU_BORDER) {                      // flag for fp64 refinement
                int idx = atomicAdd(&g_cnt, 1);
                if (idx < MAXB) g_list[idx] = make_int2(row0 + i, col0 + j);
            }
            vo[j] = v;
            zo[j] = z;
            bo[j] = (RHO_AD * bp[j] + ONE_M_RHO * z) * am[j];
            xo[j] = ALPHA_F * xp[j] + z;
        }
        *(float4*)(out + OFF_V + base)     = make_float4(vo[0], vo[1], vo[2], vo[3]);
        *(float4*)(out + OFF_V + base + 4) = make_float4(vo[4], vo[5], vo[6], vo[7]);
        *(float4*)(out + OFF_Z + base)     = make_float4(zo[0], zo[1], zo[2], zo[3]);
        *(float4*)(out + OFF_Z + base + 4) = make_float4(zo[4], zo[5], zo[6], zo[7]);
        *(float4*)(out + OFF_X + base)     = make_float4(xo[0], xo[1], xo[2], xo[3]);
        *(float4*)(out + OFF_X + base + 4) = make_float4(xo[4], xo[5], xo[6], xo[7]);
        *(float4*)(out + OFF_B + base)     = make_float4(bo[0], bo[1], bo[2], bo[3]);
        *(float4*)(out + OFF_B + base + 4) = make_float4(bo[4], bo[5], bo[6], bo[7]);
    }
}

// ---------------------------------------------------------------------------
// Borderline refinement: recompute flagged drives exactly in fp64 (one warp
// per element), overwrite v, z, x, b. Runs before gemm2 so x is consistent.
// ---------------------------------------------------------------------------
__global__ void refine_kernel(const float* __restrict__ v_prev,
                              const float* __restrict__ z_prev,
                              const float* __restrict__ x_prev,
                              const float* __restrict__ b_prev,
                              const float* __restrict__ adapt_mask,
                              const float* __restrict__ b_in,
                              float* __restrict__ out) {
    int nitems = g_cnt < MAXB ? g_cnt : MAXB;
    int warp = (blockIdx.x * blockDim.x + threadIdx.x) >> 5;
    int lane = threadIdx.x & 31;
    int nwarps = (gridDim.x * blockDim.x) >> 5;
    for (int i = warp; i < nitems; i += nwarps) {
        int2 rc = g_list[i];
        const float* a = g_A + (size_t)rc.x * KTOT;
        const float* w = g_W + (size_t)rc.y * KTOT;
        double s = 0.0;
        for (int k = lane; k < KTOT; k += 32)
            s += (double)a[k] * (double)w[k];
#pragma unroll
        for (int o = 16; o > 0; o >>= 1)
            s += __shfl_xor_sync(0xffffffffu, s, o);
        if (lane == 0) {
            size_t idx = (size_t)rc.x * NV2 + rc.y;
            double drive = s + (double)b_in[rc.y];
            double vd = (double)BETA_MEM * (double)v_prev[idx] + drive
                        - (double)z_prev[idx];
            float bp = b_prev[idx];
            float Bth = fmaf(BETA_AD, bp, 1.0f);
            float z = (vd - (double)Bth) > 0.0 ? 1.0f : 0.0f;
            out[OFF_V + idx] = (float)vd;
            out[OFF_Z + idx] = z;
            out[OFF_X + idx] = ALPHA_F * x_prev[idx] + z;
            out[OFF_B + idx] = (RHO_AD * bp + ONE_M_RHO * z) * adapt_mask[rc.y];
        }
    }
}

// ---------------------------------------------------------------------------
// GEMM 2: logits = x @ g_W2^T + g_b2, scatter to mu/fb and fused pi softplus
//   64x128 tile, BK=16, 256 threads, 4x8/thread
// ---------------------------------------------------------------------------
#define BM2 64
#define BN2 128
#define LDS_A2 68
#define NKT2 (K2 / BK)   // 256

__global__ __launch_bounds__(256)
void gemm2_kernel(const float* __restrict__ xin, float* __restrict__ out) {
    __shared__ __align__(16) float SA[2][BK][LDS_A2];
    __shared__ __align__(16) float SB[2][BK][LDS_S];

    const int tid = threadIdx.x;
    const int tx = tid & 15;
    const int ty = tid >> 4;         // 0..15 -> 4 rows each
    const int bm = blockIdx.y, bn = blockIdx.x;

    const int lrow = tid >> 2;       // 0..63
    const int lcol = (tid & 3) << 2;

    const float* Ag = xin + (size_t)(bm * BM2 + lrow) * K2 + lcol;
    const float* Wg = g_W2 + (size_t)(bn * BN2 + lrow) * K2 + lcol;
    const size_t rstep = (size_t)64 * K2;

    unsigned long long acc[4][4];
#pragma unroll
    for (int i = 0; i < 4; i++)
#pragma unroll
        for (int j = 0; j < 4; j++) acc[i][j] = 0ull;

    float4 ra = *(const float4*)(Ag);
    float4 rb0 = *(const float4*)(Wg);
    float4 rb1 = *(const float4*)(Wg + rstep);
    {   // stash tile 0
        SA[0][lcol + 0][lrow] = ra.x; SA[0][lcol + 1][lrow] = ra.y;
        SA[0][lcol + 2][lrow] = ra.z; SA[0][lcol + 3][lrow] = ra.w;
        stash128(SB[0], lrow, lcol, rb0, rb1);
    }
    __syncthreads();

    int buf = 0;
    for (int kt = 0; kt < NKT2; kt++) {
        if (kt + 1 < NKT2) {
            const float* Ap = Ag + (size_t)(kt + 1) * BK;
            const float* Wp = Wg + (size_t)(kt + 1) * BK;
            ra = *(const float4*)(Ap);
            rb0 = *(const float4*)(Wp);
            rb1 = *(const float4*)(Wp + rstep);
        }
#pragma unroll
        for (int kk = 0; kk < BK; kk++) {
            float4 a = *(const float4*)&SA[buf][kk][ty * 4];
            ulonglong2 b01 = *(const ulonglong2*)&SB[buf][kk][tx * 8];
            ulonglong2 b23 = *(const ulonglong2*)&SB[buf][kk][tx * 8 + 4];
            unsigned long long ad[4];
            ad[0] = pack_dup(a.x); ad[1] = pack_dup(a.y);
            ad[2] = pack_dup(a.z); ad[3] = pack_dup(a.w);
#pragma unroll
            for (int i = 0; i < 4; i++) {
                ffma2(acc[i][0], ad[i], b01.x);
                ffma2(acc[i][1], ad[i], b01.y);
                ffma2(acc[i][2], ad[i], b23.x);
                ffma2(acc[i][3], ad[i], b23.y);
            }
        }
        __syncthreads();
        if (kt + 1 < NKT2) {
            int nb = buf ^ 1;
            SA[nb][lcol + 0][lrow] = ra.x; SA[nb][lcol + 1][lrow] = ra.y;
            SA[nb][lcol + 2][lrow] = ra.z; SA[nb][lcol + 3][lrow] = ra.w;
            stash128(SB[nb], lrow, lcol, rb0, rb1);
            __syncthreads();
            buf = nb;
        }
    }

    const int row0 = bm * BM2 + ty * 4;
    const int col0 = bn * BN2 + tx * 8;
    float bias[8];
    *(float4*)&bias[0] = *(const float4*)(g_b2 + col0);
    *(float4*)&bias[4] = *(const float4*)(g_b2 + col0 + 4);

#pragma unroll
    for (int i = 0; i < 4; i++) {
        const int r = row0 + i;
        float dr[8];
#pragma unroll
        for (int p = 0; p < 4; p++) {
            float2 d = unpack2(acc[i][p]);
            dr[p * 2] = d.x; dr[p * 2 + 1] = d.y;
        }
#pragma unroll
        for (int j = 0; j < 8; j++) {
            int c = col0 + j;
            float val = dr[j] + bias[j];
            if (c < N_DIM) {
                out[OFF_MU + (size_t)r * N_DIM + c] = val;               // logits (softmax later)
            } else if (c < 2 * N_DIM) {
                out[OFF_FB + (size_t)r * N_DIM + (c - N_DIM)] = val;     // feedback
            } else if (c == 2 * N_DIM) {
                float sp = fmaxf(val, 0.0f) + log1pf(expf(-fabsf(val))); // softplus
                out[OFF_PI + r] = fminf(sp, 10.0f);
            }
        }
    }
}

// ---------------------------------------------------------------------------
// Softmax over [B, 180] in place (one warp per row)
// ---------------------------------------------------------------------------
__global__ void softmax_kernel(float* __restrict__ out) {
    int warp = (blockIdx.x * blockDim.x + threadIdx.x) >> 5;
    int lane = threadIdx.x & 31;
    if (warp >= B_DIM) return;
    float* row = out + OFF_MU + (size_t)warp * N_DIM;

    float vals[6];
    float mx = -1e30f;
#pragma unroll
    for (int t = 0; t < 6; t++) {
        int j = lane + t * 32;
        vals[t] = (j < N_DIM) ? row[j] : -1e30f;
        mx = fmaxf(mx, vals[t]);
    }
#pragma unroll
    for (int o = 16; o > 0; o >>= 1) mx = fmaxf(mx, __shfl_xor_sync(0xffffffffu, mx, o));
    float s = 0.0f;
#pragma unroll
    for (int t = 0; t < 6; t++) {
        int j = lane + t * 32;
        float e = expf(vals[t] - mx);
        vals[t] = e;
        if (j < N_DIM) s += e;
    }
#pragma unroll
    for (int o = 16; o > 0; o >>= 1) s += __shfl_xor_sync(0xffffffffu, s, o);
    float inv = 1.0f / s;
#pragma unroll
    for (int t = 0; t < 6; t++) {
        int j = lane + t * 32;
        if (j < N_DIM) row[j] = vals[t] * inv;
    }
}

// ---------------------------------------------------------------------------
// Launch
// ---------------------------------------------------------------------------
extern "C" void kernel_launch(void* const* d_in, const int* in_sizes, int n_in,
                              void* d_out, int out_size) {
    const float* x_l4   = (const float*)d_in[0];
    const float* x_l23  = (const float*)d_in[1];
    const float* cue    = (const float*)d_in[2];
    const float* task   = (const float*)d_in[3];
    const float* v_prev = (const float*)d_in[4];
    const float* z_prev = (const float*)d_in[5];
    const float* x_prev = (const float*)d_in[6];
    const float* b_prev = (const float*)d_in[7];
    const float* amask  = (const float*)d_in[8];
    const float* W_in   = (const float*)d_in[9];
    const float* b_in   = (const float*)d_in[10];
    const float* W_rec  = (const float*)d_in[11];
    const float* W_mu   = (const float*)d_in[12];
    const float* b_mu   = (const float*)d_in[13];
    const float* W_fb   = (const float*)d_in[14];
    const float* b_fb   = (const float*)d_in[15];
    const float* W_pi   = (const float*)d_in[16];
    const float* b_pi   = (const float*)d_in[17];
    float* out = (float*)d_out;

    reset_kernel<<<1, 1>>>();
    pack_A_kernel<<<dim3((KTOT + 255) / 256, B_DIM), 256>>>(x_l4, x_l23, cue, task, x_prev);
    pack_W_kernel<<<dim3((KTOT + 255) / 256, NV2), 256>>>(W_in, W_rec);
    pack_W2_kernel<<<dim3((K2 + 255) / 256, N2PAD), 256>>>(W_mu, b_mu, W_fb, b_fb, W_pi, b_pi);

    gemm1_kernel<<<dim3(NV2 / BN, B_DIM / BM), 256>>>(v_prev, z_prev, x_prev, b_prev,
                                                      amask, b_in, out);
    refine_kernel<<<128, 256>>>(v_prev, z_prev, x_prev, b_prev, amask, b_in, out);
    gemm2_kernel<<<dim3(N2PAD / BN2, B_DIM / BM2), 256>>>(out + OFF_X, out);
    softmax_kernel<<<(B_DIM * 32 + 255) / 256, 256>>>(out);
}

// round 11
// speedup vs baseline: 1.6775x; 1.6775x over previous
#include <cuda_runtime.h>
#include <cuda_bf16.h>
#include <math.h>
#include <stdint.h>

// ---------------------------------------------------------------------------
// Problem constants
// ---------------------------------------------------------------------------
#define B_DIM   4096
#define N_DIM   180
#define NV2     4096
#define IN_DIM  542            // 3*N + 2
#define KACT    4638           // actual K of [inputs | x_prev]
#define K2      4096
#define N2PAD   384            // 180 + 180 + 1 padded to multiple of 128

// bf16 3-term split GEMM layout (terms: hi.hi, hi.lo, lo.hi)
#define KP      4672           // per-term K padded to multiple of 64
#define BKt     64             // bf16 elems per k-tile
#define TPT     (KP / BKt)     // 73 k-tiles per term
#define NT_G1   (3 * TPT)      // 219 total k-tiles

// Output layout (tuple flattened in return order, all fp32)
#define OFF_MU  0
#define OFF_PI  737280
#define OFF_FB  741376
#define OFF_V   1478656
#define OFF_Z   18255872
#define OFF_X   35033088
#define OFF_B   51810304

#define BETA_MEM   0.95122942450071400910f   // exp(-1/20)
#define RHO_AD     0.99501247919268232265f   // exp(-1/200)
#define ONE_M_RHO  0.00498752080731767735f
#define BETA_AD    1.8f
#define ALPHA_F    0.9f

#define TAU_BORDER 1e-4f       // |v - B_thresh| band that triggers fp64 refinement
#define MAXB       65536

// ---------------------------------------------------------------------------
// Scratch (static device globals -- no runtime allocation allowed).
// Deduplicated hi/lo buffers: ~159 MB total, matching the footprint of the
// kernels that have successfully run on this harness.
// ---------------------------------------------------------------------------
__device__ __nv_bfloat16 g_Ahi[(size_t)B_DIM * KP];   // 38.3 MB
__device__ __nv_bfloat16 g_Alo[(size_t)B_DIM * KP];   // 38.3 MB
__device__ __nv_bfloat16 g_Whi[(size_t)NV2 * KP];     // 38.3 MB
__device__ __nv_bfloat16 g_Wlo[(size_t)NV2 * KP];     // 38.3 MB
__device__ float g_W2[(size_t)N2PAD * K2];            // 6 MB
__device__ float g_b2[N2PAD];
__device__ int   g_cnt;
__device__ int2  g_list[MAXB];

// ---------------------------------------------------------------------------
// PTX helpers (base-ISA only: cp.async, ldmatrix, mma.sync -- all sm_80+)
// ---------------------------------------------------------------------------
__device__ __forceinline__ uint32_t smem_u32(const void* p) {
    uint32_t a;
    asm("{ .reg .u64 t; cvta.to.shared.u64 t, %1; cvt.u32.u64 %0, t; }" : "=r"(a) : "l"(p));
    return a;
}
__device__ __forceinline__ void cp_async16(uint32_t saddr, const void* gaddr) {
    asm volatile("cp.async.cg.shared.global [%0], [%1], 16;" :: "r"(saddr), "l"(gaddr) : "memory");
}
#define CP_COMMIT() asm volatile("cp.async.commit_group;" ::: "memory")
#define CP_WAIT1()  asm volatile("cp.async.wait_group 1;" ::: "memory")

__device__ __forceinline__ void ldm_x4(uint32_t& r0, uint32_t& r1, uint32_t& r2, uint32_t& r3,
                                       uint32_t addr) {
    asm volatile("ldmatrix.sync.aligned.m8n8.x4.shared.b16 {%0,%1,%2,%3}, [%4];"
                 : "=r"(r0), "=r"(r1), "=r"(r2), "=r"(r3) : "r"(addr));
}
__device__ __forceinline__ void mma_bf16(float& c0, float& c1, float& c2, float& c3,
                                         uint32_t a0, uint32_t a1, uint32_t a2, uint32_t a3,
                                         uint32_t b0, uint32_t b1) {
    asm volatile("mma.sync.aligned.m16n8k16.row.col.f32.bf16.bf16.f32 "
                 "{%0,%1,%2,%3}, {%4,%5,%6,%7}, {%8,%9}, {%0,%1,%2,%3};"
                 : "+f"(c0), "+f"(c1), "+f"(c2), "+f"(c3)
                 : "r"(a0), "r"(a1), "r"(a2), "r"(a3), "r"(b0), "r"(b1));
}

// ---------------------------------------------------------------------------
// f32x2 packed-FMA helpers (for stage-2 GEMM)
// ---------------------------------------------------------------------------
__device__ __forceinline__ unsigned long long pack_dup(float x) {
    unsigned long long r;
    asm("mov.b64 %0, {%1, %1};" : "=l"(r) : "f"(x));
    return r;
}
__device__ __forceinline__ void ffma2(unsigned long long& d,
                                      unsigned long long a,
                                      unsigned long long b) {
    asm("fma.rn.f32x2 %0, %1, %2, %0;" : "+l"(d) : "l"(a), "l"(b));
}
__device__ __forceinline__ float2 unpack2(unsigned long long v) {
    float2 r;
    asm("mov.b64 {%0, %1}, %2;" : "=f"(r.x), "=f"(r.y) : "l"(v));
    return r;
}

// ---------------------------------------------------------------------------
// Piecewise input accessors (k in [0, KACT))
// ---------------------------------------------------------------------------
__device__ __forceinline__ float a_elem(int b, int k,
        const float* x_l4, const float* x_l23, const float* cue,
        const float* task, const float* x_prev) {
    if (k < N_DIM)            return x_l4[b * N_DIM + k];
    if (k < 2 * N_DIM)        return x_l23[b * N_DIM + (k - N_DIM)];
    if (k < 3 * N_DIM)        return cue[b * N_DIM + (k - 2 * N_DIM)];
    if (k < IN_DIM)           return task[b * 2 + (k - 3 * N_DIM)];
    return x_prev[(size_t)b * NV2 + (k - IN_DIM)];
}
__device__ __forceinline__ float w_elem(int n, int k,
        const float* W_in, const float* W_rec) {
    if (k < IN_DIM) return W_in[(size_t)n * IN_DIM + k];
    return W_rec[(size_t)n * NV2 + (k - IN_DIM)];
}

// ---------------------------------------------------------------------------
// Reset + pack kernels
// ---------------------------------------------------------------------------
__global__ void reset_kernel() { g_cnt = 0; }

__global__ void pack_Ab_kernel(const float* __restrict__ x_l4,
                               const float* __restrict__ x_l23,
                               const float* __restrict__ cue,
                               const float* __restrict__ task,
                               const float* __restrict__ x_prev) {
    int b = blockIdx.y;
    int k = blockIdx.x * blockDim.x + threadIdx.x;
    if (k >= KP) return;
    float v = (k < KACT) ? a_elem(b, k, x_l4, x_l23, cue, task, x_prev) : 0.0f;
    __nv_bfloat16 hi = __float2bfloat16(v);
    __nv_bfloat16 lo = __float2bfloat16(v - __bfloat162float(hi));
    size_t idx = (size_t)b * KP + k;
    g_Ahi[idx] = hi;
    g_Alo[idx] = lo;
}

__global__ void pack_Wb_kernel(const float* __restrict__ W_in,
                               const float* __restrict__ W_rec) {
    int n = blockIdx.y;
    int k = blockIdx.x * blockDim.x + threadIdx.x;
    if (k >= KP) return;
    float v = (k < KACT) ? w_elem(n, k, W_in, W_rec) : 0.0f;
    __nv_bfloat16 hi = __float2bfloat16(v);
    __nv_bfloat16 lo = __float2bfloat16(v - __bfloat162float(hi));
    size_t idx = (size_t)n * KP + k;
    g_Whi[idx] = hi;
    g_Wlo[idx] = lo;
}

__global__ void pack_W2_kernel(const float* __restrict__ W_mu, const float* __restrict__ b_mu,
                               const float* __restrict__ W_fb, const float* __restrict__ b_fb,
                               const float* __restrict__ W_pi, const float* __restrict__ b_pi) {
    int r = blockIdx.y;
    int k = blockIdx.x * blockDim.x + threadIdx.x;
    if (k >= K2) return;
    float v = 0.0f;
    if (r < N_DIM)            v = W_mu[(size_t)r * K2 + k];
    else if (r < 2 * N_DIM)   v = W_fb[(size_t)(r - N_DIM) * K2 + k];
    else if (r == 2 * N_DIM)  v = W_pi[k];
    g_W2[(size_t)r * K2 + k] = v;
    if (k == 0) {
        float bb = 0.0f;
        if (r < N_DIM)           bb = b_mu[r];
        else if (r < 2 * N_DIM)  bb = b_fb[r - N_DIM];
        else if (r == 2 * N_DIM) bb = b_pi[0];
        g_b2[r] = bb;
    }
}

// ---------------------------------------------------------------------------
// GEMM 1 (mma.sync bf16): drive = sum over 3 terms of A_sel @ W_sel^T + b_in
//   term 0: A_hi.W_hi, term 1: A_hi.W_lo, term 2: A_lo.W_hi
//   CTA 128x128, BK=64, 3-stage cp.async, 8 warps (2m x 4n), warp tile 64x32.
//   Fused spiking epilogue from accumulator fragments.
// ---------------------------------------------------------------------------
#define BMt 128
#define BNt 128
#define STRIDE 144                       // bytes per smem row (128 data + 16 pad)
#define STAGE_BYTES (256 * STRIDE)       // 36864 (A: rows 0-127, B: rows 128-255)
#define STAGES 3
#define SMEM_DYN (STAGES * STAGE_BYTES)  // 110592

__device__ __forceinline__ void load_tile_g1(uint32_t s, int bm, int bn, int t, int tid) {
    // Select term buffers: t in [0, 219); term = t / 73, ktile within term.
    const int term = t / TPT;
    const int kk   = t - term * TPT;
    const __nv_bfloat16* Abase = (term < 2) ? g_Ahi : g_Alo;
    const __nv_bfloat16* Wbase = (term == 1) ? g_Wlo : g_Whi;

#pragma unroll
    for (int i = 0; i < 4; i++) {                     // A: 128 rows x 8 chunks
        int idx = tid + i * 256;
        int row = idx >> 3, ch = idx & 7;
        const char* g = (const char*)Abase
            + ((size_t)(bm * BMt + row) * KP + (size_t)kk * BKt) * 2 + ch * 16;
        cp_async16(s + row * STRIDE + ch * 16, g);
    }
#pragma unroll
    for (int i = 0; i < 4; i++) {                     // B: 128 rows x 8 chunks
        int idx = tid + i * 256;
        int row = idx >> 3, ch = idx & 7;
        const char* g = (const char*)Wbase
            + ((size_t)(bn * BNt + row) * KP + (size_t)kk * BKt) * 2 + ch * 16;
        cp_async16(s + (128 + row) * STRIDE + ch * 16, g);
    }
}

__global__ __launch_bounds__(256)
void gemm1_mma(const float* __restrict__ v_prev, const float* __restrict__ z_prev,
               const float* __restrict__ x_prev, const float* __restrict__ b_prev,
               const float* __restrict__ adapt_mask, const float* __restrict__ b_in,
               float* __restrict__ out) {
    extern __shared__ __align__(256) char smem[];
    const uint32_t sb = smem_u32(smem);
    const int tid = threadIdx.x, wid = tid >> 5, lane = tid & 31;
    const int bn = blockIdx.x, bm = blockIdx.y;
    const int wm = (wid & 1) * 64;        // warp row offset (2 warps in m)
    const int wn = (wid >> 1) * 32;       // warp col offset (4 warps in n)

    // ldmatrix lane addressing pieces
    const int lrow = lane & 15;                       // row within 16-row tile
    const int lcol = ((lane >> 4) & 1) * 8;           // 8-elem column half

    float acc[4][4][4];                               // [m-frag][n8-frag][c0..c3]
#pragma unroll
    for (int i = 0; i < 4; i++)
#pragma unroll
        for (int j = 0; j < 4; j++)
#pragma unroll
            for (int q = 0; q < 4; q++) acc[i][j][q] = 0.0f;

    // prologue: tiles 0 and 1
    load_tile_g1(sb + 0 * STAGE_BYTES, bm, bn, 0, tid); CP_COMMIT();
    load_tile_g1(sb + 1 * STAGE_BYTES, bm, bn, 1, tid); CP_COMMIT();

    for (int t = 0; t < NT_G1; t++) {
        CP_WAIT1();                    // tile t resident (≤1 group in flight)
        __syncthreads();               // all see tile t; all done computing t-1
        if (t + 2 < NT_G1)
            load_tile_g1(sb + ((t + 2) % STAGES) * STAGE_BYTES, bm, bn, t + 2, tid);
        CP_COMMIT();                   // keep group numbering uniform

        const uint32_t As = sb + (t % STAGES) * STAGE_BYTES;
        const uint32_t Bs = As + 128 * STRIDE;

#pragma unroll
        for (int ks = 0; ks < 4; ks++) {              // 4 x k16 per 64-wide tile
            const uint32_t coff = (ks * 16 + lcol) * 2;
            uint32_t a[4][4];
#pragma unroll
            for (int mf = 0; mf < 4; mf++)
                ldm_x4(a[mf][0], a[mf][1], a[mf][2], a[mf][3],
                       As + (wm + mf * 16 + lrow) * STRIDE + coff);
            uint32_t b[2][4];
#pragma unroll
            for (int nt = 0; nt < 2; nt++)
                ldm_x4(b[nt][0], b[nt][1], b[nt][2], b[nt][3],
                       Bs + (wn + nt * 16 + lrow) * STRIDE + coff);
#pragma unroll
            for (int mf = 0; mf < 4; mf++)
#pragma unroll
                for (int nf = 0; nf < 4; nf++) {
                    const int nt = nf >> 1, hi = nf & 1;
                    mma_bf16(acc[mf][nf][0], acc[mf][nf][1], acc[mf][nf][2], acc[mf][nf][3],
                             a[mf][0], a[mf][1], a[mf][2], a[mf][3],
                             b[nt][hi], b[nt][2 + hi]);
                }
        }
    }

    // --- fused spiking epilogue from fragments ---
    const int grow0 = bm * BMt + wm + (lane >> 2);
    const int gcol0 = bn * BNt + wn + (lane & 3) * 2;
#pragma unroll
    for (int mf = 0; mf < 4; mf++) {
#pragma unroll
        for (int h = 0; h < 2; h++) {
            const int row = grow0 + mf * 16 + h * 8;
#pragma unroll
            for (int nf = 0; nf < 4; nf++) {
                const int col = gcol0 + nf * 8;
                const size_t o = (size_t)row * NV2 + col;
                float2 bi = *(const float2*)(b_in + col);
                float2 am = *(const float2*)(adapt_mask + col);
                float2 vp = *(const float2*)(v_prev + o);
                float2 zp = *(const float2*)(z_prev + o);
                float2 bp = *(const float2*)(b_prev + o);
                float2 xp = *(const float2*)(x_prev + o);
                float d[2] = { acc[mf][nf][h * 2 + 0], acc[mf][nf][h * 2 + 1] };
                float vo[2], zo[2], xo[2], bo[2];
#pragma unroll
                for (int j = 0; j < 2; j++) {
                    float drive = d[j] + ((const float*)&bi)[j];
                    float v = BETA_MEM * ((const float*)&vp)[j] + drive - ((const float*)&zp)[j];
                    float Bth = fmaf(BETA_AD, ((const float*)&bp)[j], 1.0f);
                    float u = v - Bth;
                    float z = u > 0.0f ? 1.0f : 0.0f;
                    if (fabsf(u) < TAU_BORDER) {
                        int idx = atomicAdd(&g_cnt, 1);
                        if (idx < MAXB) g_list[idx] = make_int2(row, col + j);
                    }
                    vo[j] = v; zo[j] = z;
                    bo[j] = (RHO_AD * ((const float*)&bp)[j] + ONE_M_RHO * z) * ((const float*)&am)[j];
                    xo[j] = ALPHA_F * ((const float*)&xp)[j] + z;
                }
                *(float2*)(out + OFF_V + o) = make_float2(vo[0], vo[1]);
                *(float2*)(out + OFF_Z + o) = make_float2(zo[0], zo[1]);
                *(float2*)(out + OFF_X + o) = make_float2(xo[0], xo[1]);
                *(float2*)(out + OFF_B + o) = make_float2(bo[0], bo[1]);
            }
        }
    }
}

// ---------------------------------------------------------------------------
// Borderline refinement: recompute flagged drives exactly in fp64 (one warp
// per element), reading the RAW fp32 inputs. Runs before gemm2.
// ---------------------------------------------------------------------------
__global__ void refine_kernel(const float* __restrict__ x_l4, const float* __restrict__ x_l23,
                              const float* __restrict__ cue, const float* __restrict__ task,
                              const float* __restrict__ v_prev, const float* __restrict__ z_prev,
                              const float* __restrict__ x_prev, const float* __restrict__ b_prev,
                              const float* __restrict__ adapt_mask,
                              const float* __restrict__ W_in, const float* __restrict__ b_in,
                              const float* __restrict__ W_rec,
                              float* __restrict__ out) {
    int nitems = g_cnt < MAXB ? g_cnt : MAXB;
    int warp = (blockIdx.x * blockDim.x + threadIdx.x) >> 5;
    int lane = threadIdx.x & 31;
    int nwarps = (gridDim.x * blockDim.x) >> 5;
    for (int i = warp; i < nitems; i += nwarps) {
        int2 rc = g_list[i];
        double s = 0.0;
        for (int k = lane; k < KACT; k += 32) {
            float a = a_elem(rc.x, k, x_l4, x_l23, cue, task, x_prev);
            float w = w_elem(rc.y, k, W_in, W_rec);
            s += (double)a * (double)w;
        }
#pragma unroll
        for (int o = 16; o > 0; o >>= 1)
            s += __shfl_xor_sync(0xffffffffu, s, o);
        if (lane == 0) {
            size_t idx = (size_t)rc.x * NV2 + rc.y;
            double drive = s + (double)b_in[rc.y];
            double vd = (double)BETA_MEM * (double)v_prev[idx] + drive - (double)z_prev[idx];
            float bp = b_prev[idx];
            float Bth = fmaf(BETA_AD, bp, 1.0f);
            float z = (vd - (double)Bth) > 0.0 ? 1.0f : 0.0f;
            out[OFF_V + idx] = (float)vd;
            out[OFF_Z + idx] = z;
            out[OFF_X + idx] = ALPHA_F * x_prev[idx] + z;
            out[OFF_B + idx] = (RHO_AD * bp + ONE_M_RHO * z) * adapt_mask[rc.y];
        }
    }
}

// ---------------------------------------------------------------------------
// GEMM 2: logits = x @ g_W2^T + g_b2 (fp32 FFMA2), scatter to mu/fb + pi
// ---------------------------------------------------------------------------
#define BK 16
#define LDS_S 132
#define BM2 64
#define BN2 128
#define LDS_A2 68
#define NKT2 (K2 / BK)

__device__ __forceinline__ void stash128(float (*S)[LDS_S], int lrow, int lcol,
                                         float4 r0, float4 r1) {
    S[lcol + 0][lrow] = r0.x; S[lcol + 1][lrow] = r0.y;
    S[lcol + 2][lrow] = r0.z; S[lcol + 3][lrow] = r0.w;
    S[lcol + 0][lrow + 64] = r1.x; S[lcol + 1][lrow + 64] = r1.y;
    S[lcol + 2][lrow + 64] = r1.z; S[lcol + 3][lrow + 64] = r1.w;
}

__global__ __launch_bounds__(256)
void gemm2_kernel(const float* __restrict__ xin, float* __restrict__ out) {
    __shared__ __align__(16) float SA[2][BK][LDS_A2];
    __shared__ __align__(16) float SB[2][BK][LDS_S];

    const int tid = threadIdx.x;
    const int tx = tid & 15;
    const int ty = tid >> 4;
    const int bm = blockIdx.y, bn = blockIdx.x;

    const int lrow = tid >> 2;
    const int lcol = (tid & 3) << 2;

    const float* Ag = xin + (size_t)(bm * BM2 + lrow) * K2 + lcol;
    const float* Wg = g_W2 + (size_t)(bn * BN2 + lrow) * K2 + lcol;
    const size_t rstep = (size_t)64 * K2;

    unsigned long long acc[4][4];
#pragma unroll
    for (int i = 0; i < 4; i++)
#pragma unroll
        for (int j = 0; j < 4; j++) acc[i][j] = 0ull;

    float4 ra = *(const float4*)(Ag);
    float4 rb0 = *(const float4*)(Wg);
    float4 rb1 = *(const float4*)(Wg + rstep);
    {
        SA[0][lcol + 0][lrow] = ra.x; SA[0][lcol + 1][lrow] = ra.y;
        SA[0][lcol + 2][lrow] = ra.z; SA[0][lcol + 3][lrow] = ra.w;
        stash128(SB[0], lrow, lcol, rb0, rb1);
    }
    __syncthreads();

    int buf = 0;
    for (int kt = 0; kt < NKT2; kt++) {
        if (kt + 1 < NKT2) {
            const float* Ap = Ag + (size_t)(kt + 1) * BK;
            const float* Wp = Wg + (size_t)(kt + 1) * BK;
            ra = *(const float4*)(Ap);
            rb0 = *(const float4*)(Wp);
            rb1 = *(const float4*)(Wp + rstep);
        }
#pragma unroll
        for (int kk = 0; kk < BK; kk++) {
            float4 a = *(const float4*)&SA[buf][kk][ty * 4];
            ulonglong2 b01 = *(const ulonglong2*)&SB[buf][kk][tx * 8];
            ulonglong2 b23 = *(const ulonglong2*)&SB[buf][kk][tx * 8 + 4];
            unsigned long long ad[4];
            ad[0] = pack_dup(a.x); ad[1] = pack_dup(a.y);
            ad[2] = pack_dup(a.z); ad[3] = pack_dup(a.w);
#pragma unroll
            for (int i = 0; i < 4; i++) {
                ffma2(acc[i][0], ad[i], b01.x);
                ffma2(acc[i][1], ad[i], b01.y);
                ffma2(acc[i][2], ad[i], b23.x);
                ffma2(acc[i][3], ad[i], b23.y);
            }
        }
        __syncthreads();
        if (kt + 1 < NKT2) {
            int nb = buf ^ 1;
            SA[nb][lcol + 0][lrow] = ra.x; SA[nb][lcol + 1][lrow] = ra.y;
            SA[nb][lcol + 2][lrow] = ra.z; SA[nb][lcol + 3][lrow] = ra.w;
            stash128(SB[nb], lrow, lcol, rb0, rb1);
            __syncthreads();
            buf = nb;
        }
    }

    const int row0 = bm * BM2 + ty * 4;
    const int col0 = bn * BN2 + tx * 8;
    float bias[8];
    *(float4*)&bias[0] = *(const float4*)(g_b2 + col0);
    *(float4*)&bias[4] = *(const float4*)(g_b2 + col0 + 4);

#pragma unroll
    for (int i = 0; i < 4; i++) {
        const int r = row0 + i;
        float dr[8];
#pragma unroll
        for (int p = 0; p < 4; p++) {
            float2 d = unpack2(acc[i][p]);
            dr[p * 2] = d.x; dr[p * 2 + 1] = d.y;
        }
#pragma unroll
        for (int j = 0; j < 8; j++) {
            int c = col0 + j;
            float val = dr[j] + bias[j];
            if (c < N_DIM) {
                out[OFF_MU + (size_t)r * N_DIM + c] = val;
            } else if (c < 2 * N_DIM) {
                out[OFF_FB + (size_t)r * N_DIM + (c - N_DIM)] = val;
            } else if (c == 2 * N_DIM) {
                float sp = fmaxf(val, 0.0f) + log1pf(expf(-fabsf(val)));
                out[OFF_PI + r] = fminf(sp, 10.0f);
            }
        }
    }
}

// ---------------------------------------------------------------------------
// Softmax over [B, 180] in place (one warp per row)
// ---------------------------------------------------------------------------
__global__ void softmax_kernel(float* __restrict__ out) {
    int warp = (blockIdx.x * blockDim.x + threadIdx.x) >> 5;
    int lane = threadIdx.x & 31;
    if (warp >= B_DIM) return;
    float* row = out + OFF_MU + (size_t)warp * N_DIM;

    float vals[6];
    float mx = -1e30f;
#pragma unroll
    for (int t = 0; t < 6; t++) {
        int j = lane + t * 32;
        vals[t] = (j < N_DIM) ? row[j] : -1e30f;
        mx = fmaxf(mx, vals[t]);
    }
#pragma unroll
    for (int o = 16; o > 0; o >>= 1) mx = fmaxf(mx, __shfl_xor_sync(0xffffffffu, mx, o));
    float s = 0.0f;
#pragma unroll
    for (int t = 0; t < 6; t++) {
        int j = lane + t * 32;
        float e = expf(vals[t] - mx);
        vals[t] = e;
        if (j < N_DIM) s += e;
    }
#pragma unroll
    for (int o = 16; o > 0; o >>= 1) s += __shfl_xor_sync(0xffffffffu, s, o);
    float inv = 1.0f / s;
#pragma unroll
    for (int t = 0; t < 6; t++) {
        int j = lane + t * 32;
        if (j < N_DIM) row[j] = vals[t] * inv;
    }
}

// ---------------------------------------------------------------------------
// Launch
// ---------------------------------------------------------------------------
extern "C" void kernel_launch(void* const* d_in, const int* in_sizes, int n_in,
                              void* d_out, int out_size) {
    const float* x_l4   = (const float*)d_in[0];
    const float* x_l23  = (const float*)d_in[1];
    const float* cue    = (const float*)d_in[2];
    const float* task   = (const float*)d_in[3];
    const float* v_prev = (const float*)d_in[4];
    const float* z_prev = (const float*)d_in[5];
    const float* x_prev = (const float*)d_in[6];
    const float* b_prev = (const float*)d_in[7];
    const float* amask  = (const float*)d_in[8];
    const float* W_in   = (const float*)d_in[9];
    const float* b_in   = (const float*)d_in[10];
    const float* W_rec  = (const float*)d_in[11];
    const float* W_mu   = (const float*)d_in[12];
    const float* b_mu   = (const float*)d_in[13];
    const float* W_fb   = (const float*)d_in[14];
    const float* b_fb   = (const float*)d_in[15];
    const float* W_pi   = (const float*)d_in[16];
    const float* b_pi   = (const float*)d_in[17];
    float* out = (float*)d_out;

    cudaFuncSetAttribute(gemm1_mma, cudaFuncAttributeMaxDynamicSharedMemorySize, SMEM_DYN);

    reset_kernel<<<1, 1>>>();
    pack_Ab_kernel<<<dim3((KP + 255) / 256, B_DIM), 256>>>(x_l4, x_l23, cue, task, x_prev);
    pack_Wb_kernel<<<dim3((KP + 255) / 256, NV2), 256>>>(W_in, W_rec);
    pack_W2_kernel<<<dim3((K2 + 255) / 256, N2PAD), 256>>>(W_mu, b_mu, W_fb, b_fb, W_pi, b_pi);

    gemm1_mma<<<dim3(NV2 / BNt, B_DIM / BMt), 256, SMEM_DYN>>>(
        v_prev, z_prev, x_prev, b_prev, amask, b_in, out);

    refine_kernel<<<128, 256>>>(x_l4, x_l23, cue, task, v_prev, z_prev, x_prev, b_prev,
                                amask, W_in, b_in, W_rec, out);
    gemm2_kernel<<<dim3(N2PAD / BN2, B_DIM / BM2), 256>>>(out + OFF_X, out);
    softmax_kernel<<<(B_DIM * 32 + 255) / 256, 256>>>(out);
}

// round 13
// speedup vs baseline: 2.3257x; 1.3864x over previous
#include <cuda_runtime.h>
#include <cuda_fp16.h>
#include <math.h>
#include <stdint.h>

// ---------------------------------------------------------------------------
// Problem constants
// ---------------------------------------------------------------------------
#define B_DIM   4096
#define N_DIM   180
#define NV2     4096
#define IN_DIM  542            // 3*N + 2
#define KACT    4638           // actual K of [inputs | x_prev]
#define K2      4096
#define N2PAD   384            // 180 + 180 + 1 padded to multiple of 128

// single-term fp16 GEMM layout
#define KP      4672           // K padded to multiple of 64
#define BKt     64             // fp16 elems per k-tile
#define NT_G1   (KP / BKt)     // 73 k-tiles

// Output layout (tuple flattened in return order, all fp32)
#define OFF_MU  0
#define OFF_PI  737280
#define OFF_FB  741376
#define OFF_V   1478656
#define OFF_Z   18255872
#define OFF_X   35033088
#define OFF_B   51810304

#define BETA_MEM   0.95122942450071400910f   // exp(-1/20)
#define RHO_AD     0.99501247919268232265f   // exp(-1/200)
#define ONE_M_RHO  0.00498752080731767735f
#define BETA_AD    1.8f
#define ALPHA_F    0.9f

#define TAU_BORDER 1e-3f       // |v - B_thresh| band (≈6.5 sigma of fp16 GEMM error)
#define MAXB       65536

// ---------------------------------------------------------------------------
// Scratch (static device globals -- ~82 MB total, well inside proven envelope)
// ---------------------------------------------------------------------------
__device__ __half g_A16[(size_t)B_DIM * KP];   // 38.3 MB
__device__ __half g_W16[(size_t)NV2 * KP];     // 38.3 MB
__device__ float g_W2[(size_t)N2PAD * K2];     // 6 MB
__device__ float g_b2[N2PAD];
__device__ int   g_cnt;
__device__ int2  g_list[MAXB];

// ---------------------------------------------------------------------------
// PTX helpers (base-ISA only: cp.async, ldmatrix, mma.sync -- all sm_80+)
// ---------------------------------------------------------------------------
__device__ __forceinline__ uint32_t smem_u32(const void* p) {
    uint32_t a;
    asm("{ .reg .u64 t; cvta.to.shared.u64 t, %1; cvt.u32.u64 %0, t; }" : "=r"(a) : "l"(p));
    return a;
}
__device__ __forceinline__ void cp_async16(uint32_t saddr, const void* gaddr) {
    asm volatile("cp.async.cg.shared.global [%0], [%1], 16;" :: "r"(saddr), "l"(gaddr) : "memory");
}
#define CP_COMMIT() asm volatile("cp.async.commit_group;" ::: "memory")
#define CP_WAIT1()  asm volatile("cp.async.wait_group 1;" ::: "memory")

__device__ __forceinline__ void ldm_x4(uint32_t& r0, uint32_t& r1, uint32_t& r2, uint32_t& r3,
                                       uint32_t addr) {
    asm volatile("ldmatrix.sync.aligned.m8n8.x4.shared.b16 {%0,%1,%2,%3}, [%4];"
                 : "=r"(r0), "=r"(r1), "=r"(r2), "=r"(r3) : "r"(addr));
}
__device__ __forceinline__ void mma_f16(float& c0, float& c1, float& c2, float& c3,
                                        uint32_t a0, uint32_t a1, uint32_t a2, uint32_t a3,
                                        uint32_t b0, uint32_t b1) {
    asm volatile("mma.sync.aligned.m16n8k16.row.col.f32.f16.f16.f32 "
                 "{%0,%1,%2,%3}, {%4,%5,%6,%7}, {%8,%9}, {%0,%1,%2,%3};"
                 : "+f"(c0), "+f"(c1), "+f"(c2), "+f"(c3)
                 : "r"(a0), "r"(a1), "r"(a2), "r"(a3), "r"(b0), "r"(b1));
}

// ---------------------------------------------------------------------------
// f32x2 packed-FMA helpers (for stage-2 GEMM)
// ---------------------------------------------------------------------------
__device__ __forceinline__ unsigned long long pack_dup(float x) {
    unsigned long long r;
    asm("mov.b64 %0, {%1, %1};" : "=l"(r) : "f"(x));
    return r;
}
__device__ __forceinline__ void ffma2(unsigned long long& d,
                                      unsigned long long a,
                                      unsigned long long b) {
    asm("fma.rn.f32x2 %0, %1, %2, %0;" : "+l"(d) : "l"(a), "l"(b));
}
__device__ __forceinline__ float2 unpack2(unsigned long long v) {
    float2 r;
    asm("mov.b64 {%0, %1}, %2;" : "=f"(r.x), "=f"(r.y) : "l"(v));
    return r;
}

// ---------------------------------------------------------------------------
// Piecewise input accessors (k in [0, KACT))
// ---------------------------------------------------------------------------
__device__ __forceinline__ float a_elem(int b, int k,
        const float* x_l4, const float* x_l23, const float* cue,
        const float* task, const float* x_prev) {
    if (k < N_DIM)            return x_l4[b * N_DIM + k];
    if (k < 2 * N_DIM)        return x_l23[b * N_DIM + (k - N_DIM)];
    if (k < 3 * N_DIM)        return cue[b * N_DIM + (k - 2 * N_DIM)];
    if (k < IN_DIM)           return task[b * 2 + (k - 3 * N_DIM)];
    return x_prev[(size_t)b * NV2 + (k - IN_DIM)];
}
__device__ __forceinline__ float w_elem(int n, int k,
        const float* W_in, const float* W_rec) {
    if (k < IN_DIM) return W_in[(size_t)n * IN_DIM + k];
    return W_rec[(size_t)n * NV2 + (k - IN_DIM)];
}

// ---------------------------------------------------------------------------
// Reset + pack kernels
// ---------------------------------------------------------------------------
__global__ void reset_kernel() { g_cnt = 0; }

__global__ void pack_A16_kernel(const float* __restrict__ x_l4,
                                const float* __restrict__ x_l23,
                                const float* __restrict__ cue,
                                const float* __restrict__ task,
                                const float* __restrict__ x_prev) {
    int b = blockIdx.y;
    int k = blockIdx.x * blockDim.x + threadIdx.x;
    if (k >= KP) return;
    float v = (k < KACT) ? a_elem(b, k, x_l4, x_l23, cue, task, x_prev) : 0.0f;
    g_A16[(size_t)b * KP + k] = __float2half_rn(v);
}

__global__ void pack_W16_kernel(const float* __restrict__ W_in,
                                const float* __restrict__ W_rec) {
    int n = blockIdx.y;
    int k = blockIdx.x * blockDim.x + threadIdx.x;
    if (k >= KP) return;
    float v = (k < KACT) ? w_elem(n, k, W_in, W_rec) : 0.0f;
    g_W16[(size_t)n * KP + k] = __float2half_rn(v);
}

__global__ void pack_W2_kernel(const float* __restrict__ W_mu, const float* __restrict__ b_mu,
                               const float* __restrict__ W_fb, const float* __restrict__ b_fb,
                               const float* __restrict__ W_pi, const float* __restrict__ b_pi) {
    int r = blockIdx.y;
    int k = blockIdx.x * blockDim.x + threadIdx.x;
    if (k >= K2) return;
    float v = 0.0f;
    if (r < N_DIM)            v = W_mu[(size_t)r * K2 + k];
    else if (r < 2 * N_DIM)   v = W_fb[(size_t)(r - N_DIM) * K2 + k];
    else if (r == 2 * N_DIM)  v = W_pi[k];
    g_W2[(size_t)r * K2 + k] = v;
    if (k == 0) {
        float bb = 0.0f;
        if (r < N_DIM)           bb = b_mu[r];
        else if (r < 2 * N_DIM)  bb = b_fb[r - N_DIM];
        else if (r == 2 * N_DIM) bb = b_pi[0];
        g_b2[r] = bb;
    }
}

// ---------------------------------------------------------------------------
// GEMM 1 (mma.sync fp16): drive = A16 @ W16^T + b_in (single term, K=4672)
//   CTA 128x128, BK=64, 3-stage cp.async, 8 warps (2m x 4n), warp tile 64x32.
//   Fused spiking epilogue from accumulator fragments + borderline flags.
// ---------------------------------------------------------------------------
#define BMt 128
#define BNt 128
#define STRIDE 144                       // bytes per smem row (128 data + 16 pad)
#define STAGE_BYTES (256 * STRIDE)       // 36864 (A: rows 0-127, B: rows 128-255)
#define STAGES 3
#define SMEM_DYN (STAGES * STAGE_BYTES)  // 110592

__device__ __forceinline__ void load_tile_g1(uint32_t s, int bm, int bn, int t, int tid) {
#pragma unroll
    for (int i = 0; i < 4; i++) {                     // A: 128 rows x 8 chunks
        int idx = tid + i * 256;
        int row = idx >> 3, ch = idx & 7;
        const char* g = (const char*)g_A16
            + ((size_t)(bm * BMt + row) * KP + (size_t)t * BKt) * 2 + ch * 16;
        cp_async16(s + row * STRIDE + ch * 16, g);
    }
#pragma unroll
    for (int i = 0; i < 4; i++) {                     // B: 128 rows x 8 chunks
        int idx = tid + i * 256;
        int row = idx >> 3, ch = idx & 7;
        const char* g = (const char*)g_W16
            + ((size_t)(bn * BNt + row) * KP + (size_t)t * BKt) * 2 + ch * 16;
        cp_async16(s + (128 + row) * STRIDE + ch * 16, g);
    }
}

__global__ __launch_bounds__(256)
void gemm1_mma(const float* __restrict__ v_prev, const float* __restrict__ z_prev,
               const float* __restrict__ x_prev, const float* __restrict__ b_prev,
               const float* __restrict__ adapt_mask, const float* __restrict__ b_in,
               float* __restrict__ out) {
    extern __shared__ __align__(256) char smem[];
    const uint32_t sb = smem_u32(smem);
    const int tid = threadIdx.x, wid = tid >> 5, lane = tid & 31;
    const int bn = blockIdx.x, bm = blockIdx.y;
    const int wm = (wid & 1) * 64;        // warp row offset (2 warps in m)
    const int wn = (wid >> 1) * 32;       // warp col offset (4 warps in n)

    const int lrow = lane & 15;                       // row within 16-row tile
    const int lcol = ((lane >> 4) & 1) * 8;           // 8-elem column half

    float acc[4][4][4];                               // [m-frag][n8-frag][c0..c3]
#pragma unroll
    for (int i = 0; i < 4; i++)
#pragma unroll
        for (int j = 0; j < 4; j++)
#pragma unroll
            for (int q = 0; q < 4; q++) acc[i][j][q] = 0.0f;

    // prologue: tiles 0 and 1
    load_tile_g1(sb + 0 * STAGE_BYTES, bm, bn, 0, tid); CP_COMMIT();
    load_tile_g1(sb + 1 * STAGE_BYTES, bm, bn, 1, tid); CP_COMMIT();

    for (int t = 0; t < NT_G1; t++) {
        CP_WAIT1();                    // tile t resident (≤1 group in flight)
        __syncthreads();               // all see tile t; all done computing t-1
        if (t + 2 < NT_G1)
            load_tile_g1(sb + ((t + 2) % STAGES) * STAGE_BYTES, bm, bn, t + 2, tid);
        CP_COMMIT();                   // keep group numbering uniform

        const uint32_t As = sb + (t % STAGES) * STAGE_BYTES;
        const uint32_t Bs = As + 128 * STRIDE;

#pragma unroll
        for (int ks = 0; ks < 4; ks++) {              // 4 x k16 per 64-wide tile
            const uint32_t coff = (ks * 16 + lcol) * 2;
            uint32_t a[4][4];
#pragma unroll
            for (int mf = 0; mf < 4; mf++)
                ldm_x4(a[mf][0], a[mf][1], a[mf][2], a[mf][3],
                       As + (wm + mf * 16 + lrow) * STRIDE + coff);
            uint32_t b[2][4];
#pragma unroll
            for (int nt = 0; nt < 2; nt++)
                ldm_x4(b[nt][0], b[nt][1], b[nt][2], b[nt][3],
                       Bs + (wn + nt * 16 + lrow) * STRIDE + coff);
#pragma unroll
            for (int mf = 0; mf < 4; mf++)
#pragma unroll
                for (int nf = 0; nf < 4; nf++) {
                    const int nt = nf >> 1, hi = nf & 1;
                    mma_f16(acc[mf][nf][0], acc[mf][nf][1], acc[mf][nf][2], acc[mf][nf][3],
                            a[mf][0], a[mf][1], a[mf][2], a[mf][3],
                            b[nt][hi], b[nt][2 + hi]);
                }
        }
    }

    // --- fused spiking epilogue from fragments ---
    const int grow0 = bm * BMt + wm + (lane >> 2);
    const int gcol0 = bn * BNt + wn + (lane & 3) * 2;
#pragma unroll
    for (int mf = 0; mf < 4; mf++) {
#pragma unroll
        for (int h = 0; h < 2; h++) {
            const int row = grow0 + mf * 16 + h * 8;
#pragma unroll
            for (int nf = 0; nf < 4; nf++) {
                const int col = gcol0 + nf * 8;
                const size_t o = (size_t)row * NV2 + col;
                float2 bi = *(const float2*)(b_in + col);
                float2 am = *(const float2*)(adapt_mask + col);
                float2 vp = *(const float2*)(v_prev + o);
                float2 zp = *(const float2*)(z_prev + o);
                float2 bp = *(const float2*)(b_prev + o);
                float2 xp = *(const float2*)(x_prev + o);
                float d[2] = { acc[mf][nf][h * 2 + 0], acc[mf][nf][h * 2 + 1] };
                float vo[2], zo[2], xo[2], bo[2];
#pragma unroll
                for (int j = 0; j < 2; j++) {
                    float drive = d[j] + ((const float*)&bi)[j];
                    float v = BETA_MEM * ((const float*)&vp)[j] + drive - ((const float*)&zp)[j];
                    float Bth = fmaf(BETA_AD, ((const float*)&bp)[j], 1.0f);
                    float u = v - Bth;
                    float z = u > 0.0f ? 1.0f : 0.0f;
                    if (fabsf(u) < TAU_BORDER) {
                        int idx = atomicAdd(&g_cnt, 1);
                        if (idx < MAXB) g_list[idx] = make_int2(row, col + j);
                    }
                    vo[j] = v; zo[j] = z;
                    bo[j] = (RHO_AD * ((const float*)&bp)[j] + ONE_M_RHO * z) * ((const float*)&am)[j];
                    xo[j] = ALPHA_F * ((const float*)&xp)[j] + z;
                }
                *(float2*)(out + OFF_V + o) = make_float2(vo[0], vo[1]);
                *(float2*)(out + OFF_Z + o) = make_float2(zo[0], zo[1]);
                *(float2*)(out + OFF_X + o) = make_float2(xo[0], xo[1]);
                *(float2*)(out + OFF_B + o) = make_float2(bo[0], bo[1]);
            }
        }
    }
}

// ---------------------------------------------------------------------------
// Borderline refinement: recompute flagged drives exactly in fp64 (one warp
// per element), reading the RAW fp32 inputs. Overwrites v, z, x, b.
// ---------------------------------------------------------------------------
__global__ void refine_kernel(const float* __restrict__ x_l4, const float* __restrict__ x_l23,
                              const float* __restrict__ cue, const float* __restrict__ task,
                              const float* __restrict__ v_prev, const float* __restrict__ z_prev,
                              const float* __restrict__ x_prev, const float* __restrict__ b_prev,
                              const float* __restrict__ adapt_mask,
                              const float* __restrict__ W_in, const float* __restrict__ b_in,
                              const float* __restrict__ W_rec,
                              float* __restrict__ out) {
    int nitems = g_cnt < MAXB ? g_cnt : MAXB;
    int warp = (blockIdx.x * blockDim.x + threadIdx.x) >> 5;
    int lane = threadIdx.x & 31;
    int nwarps = (gridDim.x * blockDim.x) >> 5;
    for (int i = warp; i < nitems; i += nwarps) {
        int2 rc = g_list[i];
        double s = 0.0;
        for (int k = lane; k < KACT; k += 32) {
            float a = a_elem(rc.x, k, x_l4, x_l23, cue, task, x_prev);
            float w = w_elem(rc.y, k, W_in, W_rec);
            s += (double)a * (double)w;
        }
#pragma unroll
        for (int o = 16; o > 0; o >>= 1)
            s += __shfl_xor_sync(0xffffffffu, s, o);
        if (lane == 0) {
            size_t idx = (size_t)rc.x * NV2 + rc.y;
            double drive = s + (double)b_in[rc.y];
            double vd = (double)BETA_MEM * (double)v_prev[idx] + drive - (double)z_prev[idx];
            float bp = b_prev[idx];
            float Bth = fmaf(BETA_AD, bp, 1.0f);
            float z = (vd - (double)Bth) > 0.0 ? 1.0f : 0.0f;
            out[OFF_V + idx] = (float)vd;
            out[OFF_Z + idx] = z;
            out[OFF_X + idx] = ALPHA_F * x_prev[idx] + z;
            out[OFF_B + idx] = (RHO_AD * bp + ONE_M_RHO * z) * adapt_mask[rc.y];
        }
    }
}

// ---------------------------------------------------------------------------
// GEMM 2: logits = x @ g_W2^T + g_b2 (fp32 FFMA2), scatter to mu/fb + pi
// ---------------------------------------------------------------------------
#define BK 16
#define LDS_S 132
#define BM2 64
#define BN2 128
#define LDS_A2 68
#define NKT2 (K2 / BK)

__device__ __forceinline__ void stash128(float (*S)[LDS_S], int lrow, int lcol,
                                         float4 r0, float4 r1) {
    S[lcol + 0][lrow] = r0.x; S[lcol + 1][lrow] = r0.y;
    S[lcol + 2][lrow] = r0.z; S[lcol + 3][lrow] = r0.w;
    S[lcol + 0][lrow + 64] = r1.x; S[lcol + 1][lrow + 64] = r1.y;
    S[lcol + 2][lrow + 64] = r1.z; S[lcol + 3][lrow + 64] = r1.w;
}

__global__ __launch_bounds__(256)
void gemm2_kernel(const float* __restrict__ xin, float* __restrict__ out) {
    __shared__ __align__(16) float SA[2][BK][LDS_A2];
    __shared__ __align__(16) float SB[2][BK][LDS_S];

    const int tid = threadIdx.x;
    const int tx = tid & 15;
    const int ty = tid >> 4;
    const int bm = blockIdx.y, bn = blockIdx.x;

    const int lrow = tid >> 2;
    const int lcol = (tid & 3) << 2;

    const float* Ag = xin + (size_t)(bm * BM2 + lrow) * K2 + lcol;
    const float* Wg = g_W2 + (size_t)(bn * BN2 + lrow) * K2 + lcol;
    const size_t rstep = (size_t)64 * K2;

    unsigned long long acc[4][4];
#pragma unroll
    for (int i = 0; i < 4; i++)
#pragma unroll
        for (int j = 0; j < 4; j++) acc[i][j] = 0ull;

    float4 ra = *(const float4*)(Ag);
    float4 rb0 = *(const float4*)(Wg);
    float4 rb1 = *(const float4*)(Wg + rstep);
    {
        SA[0][lcol + 0][lrow] = ra.x; SA[0][lcol + 1][lrow] = ra.y;
        SA[0][lcol + 2][lrow] = ra.z; SA[0][lcol + 3][lrow] = ra.w;
        stash128(SB[0], lrow, lcol, rb0, rb1);
    }
    __syncthreads();

    int buf = 0;
    for (int kt = 0; kt < NKT2; kt++) {
        if (kt + 1 < NKT2) {
            const float* Ap = Ag + (size_t)(kt + 1) * BK;
            const float* Wp = Wg + (size_t)(kt + 1) * BK;
            ra = *(const float4*)(Ap);
            rb0 = *(const float4*)(Wp);
            rb1 = *(const float4*)(Wp + rstep);
        }
#pragma unroll
        for (int kk = 0; kk < BK; kk++) {
            float4 a = *(const float4*)&SA[buf][kk][ty * 4];
            ulonglong2 b01 = *(const ulonglong2*)&SB[buf][kk][tx * 8];
            ulonglong2 b23 = *(const ulonglong2*)&SB[buf][kk][tx * 8 + 4];
            unsigned long long ad[4];
            ad[0] = pack_dup(a.x); ad[1] = pack_dup(a.y);
            ad[2] = pack_dup(a.z); ad[3] = pack_dup(a.w);
#pragma unroll
            for (int i = 0; i < 4; i++) {
                ffma2(acc[i][0], ad[i], b01.x);
                ffma2(acc[i][1], ad[i], b01.y);
                ffma2(acc[i][2], ad[i], b23.x);
                ffma2(acc[i][3], ad[i], b23.y);
            }
        }
        __syncthreads();
        if (kt + 1 < NKT2) {
            int nb = buf ^ 1;
            SA[nb][lcol + 0][lrow] = ra.x; SA[nb][lcol + 1][lrow] = ra.y;
            SA[nb][lcol + 2][lrow] = ra.z; SA[nb][lcol + 3][lrow] = ra.w;
            stash128(SB[nb], lrow, lcol, rb0, rb1);
            __syncthreads();
            buf = nb;
        }
    }

    const int row0 = bm * BM2 + ty * 4;
    const int col0 = bn * BN2 + tx * 8;
    float bias[8];
    *(float4*)&bias[0] = *(const float4*)(g_b2 + col0);
    *(float4*)&bias[4] = *(const float4*)(g_b2 + col0 + 4);

#pragma unroll
    for (int i = 0; i < 4; i++) {
        const int r = row0 + i;
        float dr[8];
#pragma unroll
        for (int p = 0; p < 4; p++) {
            float2 d = unpack2(acc[i][p]);
            dr[p * 2] = d.x; dr[p * 2 + 1] = d.y;
        }
#pragma unroll
        for (int j = 0; j < 8; j++) {
            int c = col0 + j;
            float val = dr[j] + bias[j];
            if (c < N_DIM) {
                out[OFF_MU + (size_t)r * N_DIM + c] = val;
            } else if (c < 2 * N_DIM) {
                out[OFF_FB + (size_t)r * N_DIM + (c - N_DIM)] = val;
            } else if (c == 2 * N_DIM) {
                float sp = fmaxf(val, 0.0f) + log1pf(expf(-fabsf(val)));
                out[OFF_PI + r] = fminf(sp, 10.0f);
            }
        }
    }
}

// ---------------------------------------------------------------------------
// Softmax over [B, 180] in place (one warp per row)
// ---------------------------------------------------------------------------
__global__ void softmax_kernel(float* __restrict__ out) {
    int warp = (blockIdx.x * blockDim.x + threadIdx.x) >> 5;
    int lane = threadIdx.x & 31;
    if (warp >= B_DIM) return;
    float* row = out + OFF_MU + (size_t)warp * N_DIM;

    float vals[6];
    float mx = -1e30f;
#pragma unroll
    for (int t = 0; t < 6; t++) {
        int j = lane + t * 32;
        vals[t] = (j < N_DIM) ? row[j] : -1e30f;
        mx = fmaxf(mx, vals[t]);
    }
#pragma unroll
    for (int o = 16; o > 0; o >>= 1) mx = fmaxf(mx, __shfl_xor_sync(0xffffffffu, mx, o));
    float s = 0.0f;
#pragma unroll
    for (int t = 0; t < 6; t++) {
        int j = lane + t * 32;
        float e = expf(vals[t] - mx);
        vals[t] = e;
        if (j < N_DIM) s += e;
    }
#pragma unroll
    for (int o = 16; o > 0; o >>= 1) s += __shfl_xor_sync(0xffffffffu, s, o);
    float inv = 1.0f / s;
#pragma unroll
    for (int t = 0; t < 6; t++) {
        int j = lane + t * 32;
        if (j < N_DIM) row[j] = vals[t] * inv;
    }
}

// ---------------------------------------------------------------------------
// Launch (gemm1 placed at capture slot 4; pack_W2 deferred -- only gemm2 needs it)
// ---------------------------------------------------------------------------
extern "C" void kernel_launch(void* const* d_in, const int* in_sizes, int n_in,
                              void* d_out, int out_size) {
    const float* x_l4   = (const float*)d_in[0];
    const float* x_l23  = (const float*)d_in[1];
    const float* cue    = (const float*)d_in[2];
    const float* task   = (const float*)d_in[3];
    const float* v_prev = (const float*)d_in[4];
    const float* z_prev = (const float*)d_in[5];
    const float* x_prev = (const float*)d_in[6];
    const float* b_prev = (const float*)d_in[7];
    const float* amask  = (const float*)d_in[8];
    const float* W_in   = (const float*)d_in[9];
    const float* b_in   = (const float*)d_in[10];
    const float* W_rec  = (const float*)d_in[11];
    const float* W_mu   = (const float*)d_in[12];
    const float* b_mu   = (const float*)d_in[13];
    const float* W_fb   = (const float*)d_in[14];
    const float* b_fb   = (const float*)d_in[15];
    const float* W_pi   = (const float*)d_in[16];
    const float* b_pi   = (const float*)d_in[17];
    float* out = (float*)d_out;

    cudaFuncSetAttribute(gemm1_mma, cudaFuncAttributeMaxDynamicSharedMemorySize, SMEM_DYN);

    reset_kernel<<<1, 1>>>();
    pack_A16_kernel<<<dim3((KP + 255) / 256, B_DIM), 256>>>(x_l4, x_l23, cue, task, x_prev);
    pack_W16_kernel<<<dim3((KP + 255) / 256, NV2), 256>>>(W_in, W_rec);

    gemm1_mma<<<dim3(NV2 / BNt, B_DIM / BMt), 256, SMEM_DYN>>>(
        v_prev, z_prev, x_prev, b_prev, amask, b_in, out);

    refine_kernel<<<128, 256>>>(x_l4, x_l23, cue, task, v_prev, z_prev, x_prev, b_prev,
                                amask, W_in, b_in, W_rec, out);
    pack_W2_kernel<<<dim3((K2 + 255) / 256, N2PAD), 256>>>(W_mu, b_mu, W_fb, b_fb, W_pi, b_pi);
    gemm2_kernel<<<dim3(N2PAD / BN2, B_DIM / BM2), 256>>>(out + OFF_X, out);
    softmax_kernel<<<(B_DIM * 32 + 255) / 256, 256>>>(out);
}

// round 14
// speedup vs baseline: 3.2966x; 1.4175x over previous
#include <cuda_runtime.h>
#include <cuda_fp16.h>
#include <math.h>
#include <stdint.h>

// ---------------------------------------------------------------------------
// Problem constants
// ---------------------------------------------------------------------------
#define B_DIM   4096
#define N_DIM   180
#define NV2     4096
#define IN_DIM  542            // 3*N + 2
#define KACT    4638           // actual K of [inputs | x_prev]
#define K2      4096
#define N2PAD   384            // 180 + 180 + 1 padded to multiple of 128

// single-term fp16 GEMM-1 layout
#define KP      4672           // K padded to multiple of 64
#define BKt     64             // fp16 elems per k-tile
#define NT_G1   (KP / BKt)     // 73 k-tiles

// 2-term fp16 GEMM-2 layout (x single, W2 split hi/lo): K tiles = 2 * 64
#define NT_G2   128

// Output layout (tuple flattened in return order, all fp32)
#define OFF_MU  0
#define OFF_PI  737280
#define OFF_FB  741376
#define OFF_V   1478656
#define OFF_Z   18255872
#define OFF_X   35033088
#define OFF_B   51810304

#define BETA_MEM   0.95122942450071400910f   // exp(-1/20)
#define RHO_AD     0.99501247919268232265f   // exp(-1/200)
#define ONE_M_RHO  0.00498752080731767735f
#define BETA_AD    1.8f
#define ALPHA_F    0.9f

#define TAU_BORDER 1e-3f       // |v - B_thresh| band (≈6.5 sigma of fp16 GEMM error)
#define MAXB       65536

// ---------------------------------------------------------------------------
// Scratch (static device globals -- ~117 MB total, inside proven envelope)
// ---------------------------------------------------------------------------
__device__ __half g_A16[(size_t)B_DIM * KP];    // 38.3 MB
__device__ __half g_W16[(size_t)NV2 * KP];      // 38.3 MB
__device__ __half g_x16[(size_t)B_DIM * K2];    // 33.6 MB (stage-2 A operand)
__device__ __half g_W2h[(size_t)N2PAD * K2];    // 3 MB
__device__ __half g_W2l[(size_t)N2PAD * K2];    // 3 MB
__device__ float g_b2[N2PAD];
__device__ int   g_cnt;
__device__ int2  g_list[MAXB];

// ---------------------------------------------------------------------------
// PTX helpers (base-ISA only: cp.async, ldmatrix, mma.sync -- all sm_80+)
// ---------------------------------------------------------------------------
__device__ __forceinline__ uint32_t smem_u32(const void* p) {
    uint32_t a;
    asm("{ .reg .u64 t; cvta.to.shared.u64 t, %1; cvt.u32.u64 %0, t; }" : "=r"(a) : "l"(p));
    return a;
}
__device__ __forceinline__ void cp_async16(uint32_t saddr, const void* gaddr) {
    asm volatile("cp.async.cg.shared.global [%0], [%1], 16;" :: "r"(saddr), "l"(gaddr) : "memory");
}
#define CP_COMMIT() asm volatile("cp.async.commit_group;" ::: "memory")
#define CP_WAIT0()  asm volatile("cp.async.wait_group 0;" ::: "memory")
#define CP_WAIT1()  asm volatile("cp.async.wait_group 1;" ::: "memory")

__device__ __forceinline__ void ldm_x4(uint32_t& r0, uint32_t& r1, uint32_t& r2, uint32_t& r3,
                                       uint32_t addr) {
    asm volatile("ldmatrix.sync.aligned.m8n8.x4.shared.b16 {%0,%1,%2,%3}, [%4];"
                 : "=r"(r0), "=r"(r1), "=r"(r2), "=r"(r3) : "r"(addr));
}
__device__ __forceinline__ void mma_f16(float& c0, float& c1, float& c2, float& c3,
                                        uint32_t a0, uint32_t a1, uint32_t a2, uint32_t a3,
                                        uint32_t b0, uint32_t b1) {
    asm volatile("mma.sync.aligned.m16n8k16.row.col.f32.f16.f16.f32 "
                 "{%0,%1,%2,%3}, {%4,%5,%6,%7}, {%8,%9}, {%0,%1,%2,%3};"
                 : "+f"(c0), "+f"(c1), "+f"(c2), "+f"(c3)
                 : "r"(a0), "r"(a1), "r"(a2), "r"(a3), "r"(b0), "r"(b1));
}

// ---------------------------------------------------------------------------
// Piecewise input accessors (k in [0, KACT))
// ---------------------------------------------------------------------------
__device__ __forceinline__ float a_elem(int b, int k,
        const float* x_l4, const float* x_l23, const float* cue,
        const float* task, const float* x_prev) {
    if (k < N_DIM)            return x_l4[b * N_DIM + k];
    if (k < 2 * N_DIM)        return x_l23[b * N_DIM + (k - N_DIM)];
    if (k < 3 * N_DIM)        return cue[b * N_DIM + (k - 2 * N_DIM)];
    if (k < IN_DIM)           return task[b * 2 + (k - 3 * N_DIM)];
    return x_prev[(size_t)b * NV2 + (k - IN_DIM)];
}
__device__ __forceinline__ float w_elem(int n, int k,
        const float* W_in, const float* W_rec) {
    if (k < IN_DIM) return W_in[(size_t)n * IN_DIM + k];
    return W_rec[(size_t)n * NV2 + (k - IN_DIM)];
}

// ---------------------------------------------------------------------------
// Reset + pack kernels
// ---------------------------------------------------------------------------
__global__ void reset_kernel() { g_cnt = 0; }

__global__ void pack_A16_kernel(const float* __restrict__ x_l4,
                                const float* __restrict__ x_l23,
                                const float* __restrict__ cue,
                                const float* __restrict__ task,
                                const float* __restrict__ x_prev) {
    int b = blockIdx.y;
    int k = blockIdx.x * blockDim.x + threadIdx.x;
    if (k >= KP) return;
    float v = (k < KACT) ? a_elem(b, k, x_l4, x_l23, cue, task, x_prev) : 0.0f;
    g_A16[(size_t)b * KP + k] = __float2half_rn(v);
}

__global__ void pack_W16_kernel(const float* __restrict__ W_in,
                                const float* __restrict__ W_rec) {
    int n = blockIdx.y;
    int k = blockIdx.x * blockDim.x + threadIdx.x;
    if (k >= KP) return;
    float v = (k < KACT) ? w_elem(n, k, W_in, W_rec) : 0.0f;
    g_W16[(size_t)n * KP + k] = __float2half_rn(v);
}

// x (post-refine) -> fp16 for stage-2 A operand
__global__ void pack_x16_kernel(const float* __restrict__ xin) {
    size_t i = (size_t)blockIdx.x * blockDim.x + threadIdx.x;
    if (i >= (size_t)B_DIM * K2) return;
    g_x16[i] = __float2half_rn(xin[i]);
}

// W2 rows (mu | fb | pi | pad) -> fp16 hi/lo split + fp32 bias
__global__ void pack_W2_kernel(const float* __restrict__ W_mu, const float* __restrict__ b_mu,
                               const float* __restrict__ W_fb, const float* __restrict__ b_fb,
                               const float* __restrict__ W_pi, const float* __restrict__ b_pi) {
    int r = blockIdx.y;
    int k = blockIdx.x * blockDim.x + threadIdx.x;
    if (k >= K2) return;
    float v = 0.0f;
    if (r < N_DIM)            v = W_mu[(size_t)r * K2 + k];
    else if (r < 2 * N_DIM)   v = W_fb[(size_t)(r - N_DIM) * K2 + k];
    else if (r == 2 * N_DIM)  v = W_pi[k];
    __half hi = __float2half_rn(v);
    __half lo = __float2half_rn(v - __half2float(hi));
    g_W2h[(size_t)r * K2 + k] = hi;
    g_W2l[(size_t)r * K2 + k] = lo;
    if (k == 0) {
        float bb = 0.0f;
        if (r < N_DIM)           bb = b_mu[r];
        else if (r < 2 * N_DIM)  bb = b_fb[r - N_DIM];
        else if (r == 2 * N_DIM) bb = b_pi[0];
        g_b2[r] = bb;
    }
}

// ---------------------------------------------------------------------------
// Shared GEMM geometry: CTA 128x128, BK=64, 2-stage cp.async, 8 warps (2m x 4n)
// ---------------------------------------------------------------------------
#define BMt 128
#define BNt 128
#define STRIDE 144                       // bytes per smem row (128 data + 16 pad)
#define STAGE_BYTES (256 * STRIDE)       // 36864 (A: rows 0-127, B: rows 128-255)
#define STAGES 2
#define SMEM_DYN (STAGES * STAGE_BYTES)  // 73728 -> 2 CTAs/SM

__device__ __forceinline__ void load_tile(uint32_t s, const __half* Abase, const __half* Bbase,
                                          size_t a_kstride, size_t b_kstride,
                                          int arow0, int brow0, size_t akoff, size_t bkoff,
                                          int tid) {
#pragma unroll
    for (int i = 0; i < 4; i++) {                     // A: 128 rows x 8 chunks
        int idx = tid + i * 256;
        int row = idx >> 3, ch = idx & 7;
        const char* g = (const char*)Abase
            + ((size_t)(arow0 + row) * a_kstride + akoff) * 2 + ch * 16;
        cp_async16(s + row * STRIDE + ch * 16, g);
    }
#pragma unroll
    for (int i = 0; i < 4; i++) {                     // B: 128 rows x 8 chunks
        int idx = tid + i * 256;
        int row = idx >> 3, ch = idx & 7;
        const char* g = (const char*)Bbase
            + ((size_t)(brow0 + row) * b_kstride + bkoff) * 2 + ch * 16;
        cp_async16(s + (128 + row) * STRIDE + ch * 16, g);
    }
}

// Compute one 64-wide k-tile from smem stage into acc
__device__ __forceinline__ void mma_tile(float (&acc)[4][4][4], uint32_t As, uint32_t Bs,
                                         int wm, int wn, int lrow, int lcol) {
#pragma unroll
    for (int ks = 0; ks < 4; ks++) {
        const uint32_t coff = (ks * 16 + lcol) * 2;
        uint32_t a[4][4];
#pragma unroll
        for (int mf = 0; mf < 4; mf++)
            ldm_x4(a[mf][0], a[mf][1], a[mf][2], a[mf][3],
                   As + (wm + mf * 16 + lrow) * STRIDE + coff);
        uint32_t b[2][4];
#pragma unroll
        for (int nt = 0; nt < 2; nt++)
            ldm_x4(b[nt][0], b[nt][1], b[nt][2], b[nt][3],
                   Bs + (wn + nt * 16 + lrow) * STRIDE + coff);
#pragma unroll
        for (int mf = 0; mf < 4; mf++)
#pragma unroll
            for (int nf = 0; nf < 4; nf++) {
                const int nt = nf >> 1, hi = nf & 1;
                mma_f16(acc[mf][nf][0], acc[mf][nf][1], acc[mf][nf][2], acc[mf][nf][3],
                        a[mf][0], a[mf][1], a[mf][2], a[mf][3],
                        b[nt][hi], b[nt][2 + hi]);
            }
    }
}

// ---------------------------------------------------------------------------
// GEMM 1 (mma.sync fp16): drive = A16 @ W16^T + b_in, fused spiking epilogue
// ---------------------------------------------------------------------------
__global__ __launch_bounds__(256, 2)
void gemm1_mma(const float* __restrict__ v_prev, const float* __restrict__ z_prev,
               const float* __restrict__ x_prev, const float* __restrict__ b_prev,
               const float* __restrict__ adapt_mask, const float* __restrict__ b_in,
               float* __restrict__ out) {
    extern __shared__ __align__(256) char smem[];
    const uint32_t sb = smem_u32(smem);
    const int tid = threadIdx.x, wid = tid >> 5, lane = tid & 31;
    const int bn = blockIdx.x, bm = blockIdx.y;
    const int wm = (wid & 1) * 64;
    const int wn = (wid >> 1) * 32;
    const int lrow = lane & 15;
    const int lcol = ((lane >> 4) & 1) * 8;

    float acc[4][4][4];
#pragma unroll
    for (int i = 0; i < 4; i++)
#pragma unroll
        for (int j = 0; j < 4; j++)
#pragma unroll
            for (int q = 0; q < 4; q++) acc[i][j][q] = 0.0f;

    load_tile(sb, g_A16, g_W16, KP, KP, bm * BMt, bn * BNt, 0, 0, tid);
    CP_COMMIT();

    for (int t = 0; t < NT_G1; t++) {
        if (t + 1 < NT_G1) {
            load_tile(sb + ((t + 1) & 1) * STAGE_BYTES, g_A16, g_W16, KP, KP,
                      bm * BMt, bn * BNt, (size_t)(t + 1) * BKt, (size_t)(t + 1) * BKt, tid);
            CP_COMMIT();
            CP_WAIT1();
        } else {
            CP_WAIT0();
        }
        __syncthreads();
        const uint32_t As = sb + (t & 1) * STAGE_BYTES;
        mma_tile(acc, As, As + 128 * STRIDE, wm, wn, lrow, lcol);
        __syncthreads();
    }

    // --- fused spiking epilogue from fragments ---
    const int grow0 = bm * BMt + wm + (lane >> 2);
    const int gcol0 = bn * BNt + wn + (lane & 3) * 2;
#pragma unroll
    for (int mf = 0; mf < 4; mf++) {
#pragma unroll
        for (int h = 0; h < 2; h++) {
            const int row = grow0 + mf * 16 + h * 8;
#pragma unroll
            for (int nf = 0; nf < 4; nf++) {
                const int col = gcol0 + nf * 8;
                const size_t o = (size_t)row * NV2 + col;
                float2 bi = *(const float2*)(b_in + col);
                float2 am = *(const float2*)(adapt_mask + col);
                float2 vp = *(const float2*)(v_prev + o);
                float2 zp = *(const float2*)(z_prev + o);
                float2 bp = *(const float2*)(b_prev + o);
                float2 xp = *(const float2*)(x_prev + o);
                float d[2] = { acc[mf][nf][h * 2 + 0], acc[mf][nf][h * 2 + 1] };
                float vo[2], zo[2], xo[2], bo[2];
#pragma unroll
                for (int j = 0; j < 2; j++) {
                    float drive = d[j] + ((const float*)&bi)[j];
                    float v = BETA_MEM * ((const float*)&vp)[j] + drive - ((const float*)&zp)[j];
                    float Bth = fmaf(BETA_AD, ((const float*)&bp)[j], 1.0f);
                    float u = v - Bth;
                    float z = u > 0.0f ? 1.0f : 0.0f;
                    if (fabsf(u) < TAU_BORDER) {
                        int idx = atomicAdd(&g_cnt, 1);
                        if (idx < MAXB) g_list[idx] = make_int2(row, col + j);
                    }
                    vo[j] = v; zo[j] = z;
                    bo[j] = (RHO_AD * ((const float*)&bp)[j] + ONE_M_RHO * z) * ((const float*)&am)[j];
                    xo[j] = ALPHA_F * ((const float*)&xp)[j] + z;
                }
                *(float2*)(out + OFF_V + o) = make_float2(vo[0], vo[1]);
                *(float2*)(out + OFF_Z + o) = make_float2(zo[0], zo[1]);
                *(float2*)(out + OFF_X + o) = make_float2(xo[0], xo[1]);
                *(float2*)(out + OFF_B + o) = make_float2(bo[0], bo[1]);
            }
        }
    }
}

// ---------------------------------------------------------------------------
// GEMM 2 (mma.sync fp16, 2-term W-split): logits = x @ (W2h + W2l)^T + b2
//   K tiles: t in [0,128); term = t>>6 selects W2h/W2l, A reuses ktile t&63.
//   Epilogue scatters mu logits / fb / pi-softplus.
// ---------------------------------------------------------------------------
__global__ __launch_bounds__(256, 2)
void gemm2_mma(float* __restrict__ out) {
    extern __shared__ __align__(256) char smem[];
    const uint32_t sb = smem_u32(smem);
    const int tid = threadIdx.x, wid = tid >> 5, lane = tid & 31;
    const int bn = blockIdx.x, bm = blockIdx.y;
    const int wm = (wid & 1) * 64;
    const int wn = (wid >> 1) * 32;
    const int lrow = lane & 15;
    const int lcol = ((lane >> 4) & 1) * 8;

    float acc[4][4][4];
#pragma unroll
    for (int i = 0; i < 4; i++)
#pragma unroll
        for (int j = 0; j < 4; j++)
#pragma unroll
            for (int q = 0; q < 4; q++) acc[i][j][q] = 0.0f;

    load_tile(sb, g_x16, g_W2h, K2, K2, bm * BMt, bn * BNt, 0, 0, tid);
    CP_COMMIT();

    for (int t = 0; t < NT_G2; t++) {
        if (t + 1 < NT_G2) {
            const int tn = t + 1;
            const __half* Wb = (tn >> 6) ? g_W2l : g_W2h;
            load_tile(sb + (tn & 1) * STAGE_BYTES, g_x16, Wb, K2, K2,
                      bm * BMt, bn * BNt,
                      (size_t)(tn & 63) * BKt, (size_t)(tn & 63) * BKt, tid);
            CP_COMMIT();
            CP_WAIT1();
        } else {
            CP_WAIT0();
        }
        __syncthreads();
        const uint32_t As = sb + (t & 1) * STAGE_BYTES;
        mma_tile(acc, As, As + 128 * STRIDE, wm, wn, lrow, lcol);
        __syncthreads();
    }

    // --- scatter epilogue ---
    const int grow0 = bm * BMt + wm + (lane >> 2);
    const int gcol0 = bn * BNt + wn + (lane & 3) * 2;
#pragma unroll
    for (int mf = 0; mf < 4; mf++) {
#pragma unroll
        for (int h = 0; h < 2; h++) {
            const int r = grow0 + mf * 16 + h * 8;
#pragma unroll
            for (int nf = 0; nf < 4; nf++) {
                const int col = gcol0 + nf * 8;
#pragma unroll
                for (int j = 0; j < 2; j++) {
                    const int c = col + j;
                    float val = acc[mf][nf][h * 2 + j] + g_b2[c];
                    if (c < N_DIM) {
                        out[OFF_MU + (size_t)r * N_DIM + c] = val;
                    } else if (c < 2 * N_DIM) {
                        out[OFF_FB + (size_t)r * N_DIM + (c - N_DIM)] = val;
                    } else if (c == 2 * N_DIM) {
                        float sp = fmaxf(val, 0.0f) + log1pf(expf(-fabsf(val)));
                        out[OFF_PI + r] = fminf(sp, 10.0f);
                    }
                }
            }
        }
    }
}

// ---------------------------------------------------------------------------
// Borderline refinement: recompute flagged drives exactly in fp64 (one warp
// per element), reading the RAW fp32 inputs. Overwrites v, z, x, b.
// ---------------------------------------------------------------------------
__global__ void refine_kernel(const float* __restrict__ x_l4, const float* __restrict__ x_l23,
                              const float* __restrict__ cue, const float* __restrict__ task,
                              const float* __restrict__ v_prev, const float* __restrict__ z_prev,
                              const float* __restrict__ x_prev, const float* __restrict__ b_prev,
                              const float* __restrict__ adapt_mask,
                              const float* __restrict__ W_in, const float* __restrict__ b_in,
                              const float* __restrict__ W_rec,
                              float* __restrict__ out) {
    int nitems = g_cnt < MAXB ? g_cnt : MAXB;
    int warp = (blockIdx.x * blockDim.x + threadIdx.x) >> 5;
    int lane = threadIdx.x & 31;
    int nwarps = (gridDim.x * blockDim.x) >> 5;
    for (int i = warp; i < nitems; i += nwarps) {
        int2 rc = g_list[i];
        double s = 0.0;
        for (int k = lane; k < KACT; k += 32) {
            float a = a_elem(rc.x, k, x_l4, x_l23, cue, task, x_prev);
            float w = w_elem(rc.y, k, W_in, W_rec);
            s += (double)a * (double)w;
        }
#pragma unroll
        for (int o = 16; o > 0; o >>= 1)
            s += __shfl_xor_sync(0xffffffffu, s, o);
        if (lane == 0) {
            size_t idx = (size_t)rc.x * NV2 + rc.y;
            double drive = s + (double)b_in[rc.y];
            double vd = (double)BETA_MEM * (double)v_prev[idx] + drive - (double)z_prev[idx];
            float bp = b_prev[idx];
            float Bth = fmaf(BETA_AD, bp, 1.0f);
            float z = (vd - (double)Bth) > 0.0 ? 1.0f : 0.0f;
            out[OFF_V + idx] = (float)vd;
            out[OFF_Z + idx] = z;
            out[OFF_X + idx] = ALPHA_F * x_prev[idx] + z;
            out[OFF_B + idx] = (RHO_AD * bp + ONE_M_RHO * z) * adapt_mask[rc.y];
        }
    }
}

// ---------------------------------------------------------------------------
// Softmax over [B, 180] in place (one warp per row)
// ---------------------------------------------------------------------------
__global__ void softmax_kernel(float* __restrict__ out) {
    int warp = (blockIdx.x * blockDim.x + threadIdx.x) >> 5;
    int lane = threadIdx.x & 31;
    if (warp >= B_DIM) return;
    float* row = out + OFF_MU + (size_t)warp * N_DIM;

    float vals[6];
    float mx = -1e30f;
#pragma unroll
    for (int t = 0; t < 6; t++) {
        int j = lane + t * 32;
        vals[t] = (j < N_DIM) ? row[j] : -1e30f;
        mx = fmaxf(mx, vals[t]);
    }
#pragma unroll
    for (int o = 16; o > 0; o >>= 1) mx = fmaxf(mx, __shfl_xor_sync(0xffffffffu, mx, o));
    float s = 0.0f;
#pragma unroll
    for (int t = 0; t < 6; t++) {
        int j = lane + t * 32;
        float e = expf(vals[t] - mx);
        vals[t] = e;
        if (j < N_DIM) s += e;
    }
#pragma unroll
    for (int o = 16; o > 0; o >>= 1) s += __shfl_xor_sync(0xffffffffu, s, o);
    float inv = 1.0f / s;
#pragma unroll
    for (int t = 0; t < 6; t++) {
        int j = lane + t * 32;
        if (j < N_DIM) row[j] = vals[t] * inv;
    }
}

// ---------------------------------------------------------------------------
// Launch
// ---------------------------------------------------------------------------
extern "C" void kernel_launch(void* const* d_in, const int* in_sizes, int n_in,
                              void* d_out, int out_size) {
    const float* x_l4   = (const float*)d_in[0];
    const float* x_l23  = (const float*)d_in[1];
    const float* cue    = (const float*)d_in[2];
    const float* task   = (const float*)d_in[3];
    const float* v_prev = (const float*)d_in[4];
    const float* z_prev = (const float*)d_in[5];
    const float* x_prev = (const float*)d_in[6];
    const float* b_prev = (const float*)d_in[7];
    const float* amask  = (const float*)d_in[8];
    const float* W_in   = (const float*)d_in[9];
    const float* b_in   = (const float*)d_in[10];
    const float* W_rec  = (const float*)d_in[11];
    const float* W_mu   = (const float*)d_in[12];
    const float* b_mu   = (const float*)d_in[13];
    const float* W_fb   = (const float*)d_in[14];
    const float* b_fb   = (const float*)d_in[15];
    const float* W_pi   = (const float*)d_in[16];
    const float* b_pi   = (const float*)d_in[17];
    float* out = (float*)d_out;

    cudaFuncSetAttribute(gemm1_mma, cudaFuncAttributeMaxDynamicSharedMemorySize, SMEM_DYN);
    cudaFuncSetAttribute(gemm2_mma, cudaFuncAttributeMaxDynamicSharedMemorySize, SMEM_DYN);

    reset_kernel<<<1, 1>>>();
    pack_A16_kernel<<<dim3((KP + 255) / 256, B_DIM), 256>>>(x_l4, x_l23, cue, task, x_prev);
    pack_W16_kernel<<<dim3((KP + 255) / 256, NV2), 256>>>(W_in, W_rec);

    gemm1_mma<<<dim3(NV2 / BNt, B_DIM / BMt), 256, SMEM_DYN>>>(
        v_prev, z_prev, x_prev, b_prev, amask, b_in, out);

    refine_kernel<<<128, 256>>>(x_l4, x_l23, cue, task, v_prev, z_prev, x_prev, b_prev,
                                amask, W_in, b_in, W_rec, out);
    pack_x16_kernel<<<((int)(((size_t)B_DIM * K2 + 255) / 256)), 256>>>(out + OFF_X);
    pack_W2_kernel<<<dim3((K2 + 255) / 256, N2PAD), 256>>>(W_mu, b_mu, W_fb, b_fb, W_pi, b_pi);
    gemm2_mma<<<dim3(N2PAD / BNt, B_DIM / BMt), 256, SMEM_DYN>>>(out);
    softmax_kernel<<<(B_DIM * 32 + 255) / 256, 256>>>(out);
}

// round 15
// speedup vs baseline: 3.5826x; 1.0868x over previous
#include <cuda_runtime.h>
#include <cuda_fp16.h>
#include <math.h>
#include <stdint.h>

// ---------------------------------------------------------------------------
// Problem constants
// ---------------------------------------------------------------------------
#define B_DIM   4096
#define N_DIM   180
#define NV2     4096
#define IN_DIM  542            // 3*N + 2
#define KACT    4638           // actual K of [inputs | x_prev]
#define K2      4096
#define N2PAD   384            // 180 + 180 + 1 padded to multiple of 128

// single-term fp16 GEMM-1 layout
#define KP      4672           // K padded to multiple of 64
#define BKt     64             // fp16 elems per k-tile
#define NT_G1   (KP / BKt)     // 73 k-tiles

// 2-term fp16 GEMM-2 layout (x single, W2 split hi/lo): K tiles = 2 * 64
#define NT_G2   128

// Output layout (tuple flattened in return order, all fp32)
#define OFF_MU  0
#define OFF_PI  737280
#define OFF_FB  741376
#define OFF_V   1478656
#define OFF_Z   18255872
#define OFF_X   35033088
#define OFF_B   51810304

#define BETA_MEM   0.95122942450071400910f   // exp(-1/20)
#define RHO_AD     0.99501247919268232265f   // exp(-1/200)
#define ONE_M_RHO  0.00498752080731767735f
#define BETA_AD    1.8f
#define ALPHA_F    0.9f

#define TAU_BORDER 1e-3f       // |v - B_thresh| band (≈6.5 sigma of fp16 GEMM error)
#define MAXB       65536

// ---------------------------------------------------------------------------
// Scratch (static device globals -- ~117 MB total, inside proven envelope)
// ---------------------------------------------------------------------------
__device__ __half g_A16[(size_t)B_DIM * KP];    // 38.3 MB
__device__ __half g_W16[(size_t)NV2 * KP];      // 38.3 MB
__device__ __half g_x16[(size_t)B_DIM * K2];    // 33.6 MB (stage-2 A operand)
__device__ __half g_W2h[(size_t)N2PAD * K2];    // 3 MB
__device__ __half g_W2l[(size_t)N2PAD * K2];    // 3 MB
__device__ float g_b2[N2PAD];
__device__ int   g_cnt;
__device__ int2  g_list[MAXB];

// ---------------------------------------------------------------------------
// PTX helpers (base-ISA only: cp.async, ldmatrix, mma.sync -- all sm_80+)
// ---------------------------------------------------------------------------
__device__ __forceinline__ uint32_t smem_u32(const void* p) {
    uint32_t a;
    asm("{ .reg .u64 t; cvta.to.shared.u64 t, %1; cvt.u32.u64 %0, t; }" : "=r"(a) : "l"(p));
    return a;
}
__device__ __forceinline__ void cp_async16(uint32_t saddr, const void* gaddr) {
    asm volatile("cp.async.cg.shared.global [%0], [%1], 16;" :: "r"(saddr), "l"(gaddr) : "memory");
}
#define CP_COMMIT() asm volatile("cp.async.commit_group;" ::: "memory")
#define CP_WAIT0()  asm volatile("cp.async.wait_group 0;" ::: "memory")
#define CP_WAIT1()  asm volatile("cp.async.wait_group 1;" ::: "memory")

__device__ __forceinline__ void ldm_x4(uint32_t& r0, uint32_t& r1, uint32_t& r2, uint32_t& r3,
                                       uint32_t addr) {
    asm volatile("ldmatrix.sync.aligned.m8n8.x4.shared.b16 {%0,%1,%2,%3}, [%4];"
                 : "=r"(r0), "=r"(r1), "=r"(r2), "=r"(r3) : "r"(addr));
}
__device__ __forceinline__ void mma_f16(float& c0, float& c1, float& c2, float& c3,
                                        uint32_t a0, uint32_t a1, uint32_t a2, uint32_t a3,
                                        uint32_t b0, uint32_t b1) {
    asm volatile("mma.sync.aligned.m16n8k16.row.col.f32.f16.f16.f32 "
                 "{%0,%1,%2,%3}, {%4,%5,%6,%7}, {%8,%9}, {%0,%1,%2,%3};"
                 : "+f"(c0), "+f"(c1), "+f"(c2), "+f"(c3)
                 : "r"(a0), "r"(a1), "r"(a2), "r"(a3), "r"(b0), "r"(b1));
}

// ---------------------------------------------------------------------------
// Piecewise input accessors (k in [0, KACT))
// ---------------------------------------------------------------------------
__device__ __forceinline__ float a_elem(int b, int k,
        const float* x_l4, const float* x_l23, const float* cue,
        const float* task, const float* x_prev) {
    if (k < N_DIM)            return x_l4[b * N_DIM + k];
    if (k < 2 * N_DIM)        return x_l23[b * N_DIM + (k - N_DIM)];
    if (k < 3 * N_DIM)        return cue[b * N_DIM + (k - 2 * N_DIM)];
    if (k < IN_DIM)           return task[b * 2 + (k - 3 * N_DIM)];
    return x_prev[(size_t)b * NV2 + (k - IN_DIM)];
}
__device__ __forceinline__ float w_elem(int n, int k,
        const float* W_in, const float* W_rec) {
    if (k < IN_DIM) return W_in[(size_t)n * IN_DIM + k];
    return W_rec[(size_t)n * NV2 + (k - IN_DIM)];
}

// ---------------------------------------------------------------------------
// Pack kernels (MLP-4 per thread, uniform per-block A/W branch)
//   grid.y row in [0, 8192): row < 4096 -> A row b; else W row n = row - 4096.
//   Also zeroes g_cnt (runs before gemm1).
// ---------------------------------------------------------------------------
__global__ void pack_AW_kernel(const float* __restrict__ x_l4,
                               const float* __restrict__ x_l23,
                               const float* __restrict__ cue,
                               const float* __restrict__ task,
                               const float* __restrict__ x_prev,
                               const float* __restrict__ W_in,
                               const float* __restrict__ W_rec) {
    const int row = blockIdx.y;
    const int k0 = blockIdx.x * 1024 + threadIdx.x;
    if (row == 0 && k0 == 0) g_cnt = 0;
    if (row < B_DIM) {
        float v[4];
#pragma unroll
        for (int i = 0; i < 4; i++) {
            int k = k0 + i * 256;
            v[i] = (k < KACT) ? a_elem(row, k, x_l4, x_l23, cue, task, x_prev) : 0.0f;
        }
#pragma unroll
        for (int i = 0; i < 4; i++) {
            int k = k0 + i * 256;
            if (k < KP) g_A16[(size_t)row * KP + k] = __float2half_rn(v[i]);
        }
    } else {
        const int n = row - B_DIM;
        float v[4];
#pragma unroll
        for (int i = 0; i < 4; i++) {
            int k = k0 + i * 256;
            v[i] = (k < KACT) ? w_elem(n, k, W_in, W_rec) : 0.0f;
        }
#pragma unroll
        for (int i = 0; i < 4; i++) {
            int k = k0 + i * 256;
            if (k < KP) g_W16[(size_t)n * KP + k] = __float2half_rn(v[i]);
        }
    }
}

// W2 rows (mu | fb | pi | pad) -> fp16 hi/lo split + fp32 bias (MLP-4)
__global__ void pack_W2_kernel(const float* __restrict__ W_mu, const float* __restrict__ b_mu,
                               const float* __restrict__ W_fb, const float* __restrict__ b_fb,
                               const float* __restrict__ W_pi, const float* __restrict__ b_pi) {
    const int r = blockIdx.y;
    const int k0 = blockIdx.x * 1024 + threadIdx.x;
    const float* src = (r < N_DIM) ? (W_mu + (size_t)r * K2)
                     : (r < 2 * N_DIM) ? (W_fb + (size_t)(r - N_DIM) * K2)
                     : (r == 2 * N_DIM) ? W_pi : nullptr;
    float v[4];
#pragma unroll
    for (int i = 0; i < 4; i++) {
        int k = k0 + i * 256;
        v[i] = (src && k < K2) ? src[k] : 0.0f;
    }
#pragma unroll
    for (int i = 0; i < 4; i++) {
        int k = k0 + i * 256;
        if (k < K2) {
            __half hi = __float2half_rn(v[i]);
            __half lo = __float2half_rn(v[i] - __half2float(hi));
            g_W2h[(size_t)r * K2 + k] = hi;
            g_W2l[(size_t)r * K2 + k] = lo;
        }
    }
    if (k0 == 0) {
        float bb = 0.0f;
        if (r < N_DIM)           bb = b_mu[r];
        else if (r < 2 * N_DIM)  bb = b_fb[r - N_DIM];
        else if (r == 2 * N_DIM) bb = b_pi[0];
        g_b2[r] = bb;
    }
}

// ---------------------------------------------------------------------------
// Shared GEMM geometry: CTA 128x128, BK=64, 2-stage cp.async, 8 warps (2m x 4n)
// ---------------------------------------------------------------------------
#define BMt 128
#define BNt 128
#define STRIDE 144                       // bytes per smem row (128 data + 16 pad)
#define STAGE_BYTES (256 * STRIDE)       // 36864 (A: rows 0-127, B: rows 128-255)
#define STAGES 2
#define SMEM_DYN (STAGES * STAGE_BYTES)  // 73728

__device__ __forceinline__ void load_tile(uint32_t s, const __half* Abase, const __half* Bbase,
                                          size_t a_kstride, size_t b_kstride,
                                          int arow0, int brow0, size_t akoff, size_t bkoff,
                                          int tid) {
#pragma unroll
    for (int i = 0; i < 4; i++) {                     // A: 128 rows x 8 chunks
        int idx = tid + i * 256;
        int row = idx >> 3, ch = idx & 7;
        const char* g = (const char*)Abase
            + ((size_t)(arow0 + row) * a_kstride + akoff) * 2 + ch * 16;
        cp_async16(s + row * STRIDE + ch * 16, g);
    }
#pragma unroll
    for (int i = 0; i < 4; i++) {                     // B: 128 rows x 8 chunks
        int idx = tid + i * 256;
        int row = idx >> 3, ch = idx & 7;
        const char* g = (const char*)Bbase
            + ((size_t)(brow0 + row) * b_kstride + bkoff) * 2 + ch * 16;
        cp_async16(s + (128 + row) * STRIDE + ch * 16, g);
    }
}

// Compute one 64-wide k-tile from smem stage into acc
__device__ __forceinline__ void mma_tile(float (&acc)[4][4][4], uint32_t As, uint32_t Bs,
                                         int wm, int wn, int lrow, int lcol) {
#pragma unroll
    for (int ks = 0; ks < 4; ks++) {
        const uint32_t coff = (ks * 16 + lcol) * 2;
        uint32_t a[4][4];
#pragma unroll
        for (int mf = 0; mf < 4; mf++)
            ldm_x4(a[mf][0], a[mf][1], a[mf][2], a[mf][3],
                   As + (wm + mf * 16 + lrow) * STRIDE + coff);
        uint32_t b[2][4];
#pragma unroll
        for (int nt = 0; nt < 2; nt++)
            ldm_x4(b[nt][0], b[nt][1], b[nt][2], b[nt][3],
                   Bs + (wn + nt * 16 + lrow) * STRIDE + coff);
#pragma unroll
        for (int mf = 0; mf < 4; mf++)
#pragma unroll
            for (int nf = 0; nf < 4; nf++) {
                const int nt = nf >> 1, hi = nf & 1;
                mma_f16(acc[mf][nf][0], acc[mf][nf][1], acc[mf][nf][2], acc[mf][nf][3],
                        a[mf][0], a[mf][1], a[mf][2], a[mf][3],
                        b[nt][hi], b[nt][2 + hi]);
            }
    }
}

// ---------------------------------------------------------------------------
// GEMM 1 (mma.sync fp16): drive = A16 @ W16^T + b_in, fused spiking epilogue.
//   Epilogue also emits x as fp16 into g_x16 (stage-2 operand) -- no pack_x16.
// ---------------------------------------------------------------------------
__global__ __launch_bounds__(256, 2)
void gemm1_mma(const float* __restrict__ v_prev, const float* __restrict__ z_prev,
               const float* __restrict__ x_prev, const float* __restrict__ b_prev,
               const float* __restrict__ adapt_mask, const float* __restrict__ b_in,
               float* __restrict__ out) {
    extern __shared__ __align__(256) char smem[];
    const uint32_t sb = smem_u32(smem);
    const int tid = threadIdx.x, wid = tid >> 5, lane = tid & 31;
    const int bn = blockIdx.x, bm = blockIdx.y;
    const int wm = (wid & 1) * 64;
    const int wn = (wid >> 1) * 32;
    const int lrow = lane & 15;
    const int lcol = ((lane >> 4) & 1) * 8;

    float acc[4][4][4];
#pragma unroll
    for (int i = 0; i < 4; i++)
#pragma unroll
        for (int j = 0; j < 4; j++)
#pragma unroll
            for (int q = 0; q < 4; q++) acc[i][j][q] = 0.0f;

    load_tile(sb, g_A16, g_W16, KP, KP, bm * BMt, bn * BNt, 0, 0, tid);
    CP_COMMIT();

    for (int t = 0; t < NT_G1; t++) {
        if (t + 1 < NT_G1) {
            load_tile(sb + ((t + 1) & 1) * STAGE_BYTES, g_A16, g_W16, KP, KP,
                      bm * BMt, bn * BNt, (size_t)(t + 1) * BKt, (size_t)(t + 1) * BKt, tid);
            CP_COMMIT();
            CP_WAIT1();
        } else {
            CP_WAIT0();
        }
        __syncthreads();
        const uint32_t As = sb + (t & 1) * STAGE_BYTES;
        mma_tile(acc, As, As + 128 * STRIDE, wm, wn, lrow, lcol);
        __syncthreads();
    }

    // --- fused spiking epilogue from fragments ---
    const int grow0 = bm * BMt + wm + (lane >> 2);
    const int gcol0 = bn * BNt + wn + (lane & 3) * 2;
#pragma unroll
    for (int mf = 0; mf < 4; mf++) {
#pragma unroll
        for (int h = 0; h < 2; h++) {
            const int row = grow0 + mf * 16 + h * 8;
#pragma unroll
            for (int nf = 0; nf < 4; nf++) {
                const int col = gcol0 + nf * 8;
                const size_t o = (size_t)row * NV2 + col;
                float2 bi = *(const float2*)(b_in + col);
                float2 am = *(const float2*)(adapt_mask + col);
                float2 vp = *(const float2*)(v_prev + o);
                float2 zp = *(const float2*)(z_prev + o);
                float2 bp = *(const float2*)(b_prev + o);
                float2 xp = *(const float2*)(x_prev + o);
                float d[2] = { acc[mf][nf][h * 2 + 0], acc[mf][nf][h * 2 + 1] };
                float vo[2], zo[2], xo[2], bo[2];
#pragma unroll
                for (int j = 0; j < 2; j++) {
                    float drive = d[j] + ((const float*)&bi)[j];
                    float v = BETA_MEM * ((const float*)&vp)[j] + drive - ((const float*)&zp)[j];
                    float Bth = fmaf(BETA_AD, ((const float*)&bp)[j], 1.0f);
                    float u = v - Bth;
                    float z = u > 0.0f ? 1.0f : 0.0f;
                    if (fabsf(u) < TAU_BORDER) {
                        int idx = atomicAdd(&g_cnt, 1);
                        if (idx < MAXB) g_list[idx] = make_int2(row, col + j);
                    }
                    vo[j] = v; zo[j] = z;
                    bo[j] = (RHO_AD * ((const float*)&bp)[j] + ONE_M_RHO * z) * ((const float*)&am)[j];
                    xo[j] = ALPHA_F * ((const float*)&xp)[j] + z;
                }
                *(float2*)(out + OFF_V + o) = make_float2(vo[0], vo[1]);
                *(float2*)(out + OFF_Z + o) = make_float2(zo[0], zo[1]);
                *(float2*)(out + OFF_X + o) = make_float2(xo[0], xo[1]);
                *(float2*)(out + OFF_B + o) = make_float2(bo[0], bo[1]);
                *(__half2*)(g_x16 + o) = __floats2half2_rn(xo[0], xo[1]);
            }
        }
    }
}

// ---------------------------------------------------------------------------
// GEMM 2 (mma.sync fp16, 2-term W-split): logits = x @ (W2h + W2l)^T + b2
// ---------------------------------------------------------------------------
__global__ __launch_bounds__(256, 2)
void gemm2_mma(float* __restrict__ out) {
    extern __shared__ __align__(256) char smem[];
    const uint32_t sb = smem_u32(smem);
    const int tid = threadIdx.x, wid = tid >> 5, lane = tid & 31;
    const int bn = blockIdx.x, bm = blockIdx.y;
    const int wm = (wid & 1) * 64;
    const int wn = (wid >> 1) * 32;
    const int lrow = lane & 15;
    const int lcol = ((lane >> 4) & 1) * 8;

    float acc[4][4][4];
#pragma unroll
    for (int i = 0; i < 4; i++)
#pragma unroll
        for (int j = 0; j < 4; j++)
#pragma unroll
            for (int q = 0; q < 4; q++) acc[i][j][q] = 0.0f;

    load_tile(sb, g_x16, g_W2h, K2, K2, bm * BMt, bn * BNt, 0, 0, tid);
    CP_COMMIT();

    for (int t = 0; t < NT_G2; t++) {
        if (t + 1 < NT_G2) {
            const int tn = t + 1;
            const __half* Wb = (tn >> 6) ? g_W2l : g_W2h;
            load_tile(sb + (tn & 1) * STAGE_BYTES, g_x16, Wb, K2, K2,
                      bm * BMt, bn * BNt,
                      (size_t)(tn & 63) * BKt, (size_t)(tn & 63) * BKt, tid);
            CP_COMMIT();
            CP_WAIT1();
        } else {
            CP_WAIT0();
        }
        __syncthreads();
        const uint32_t As = sb + (t & 1) * STAGE_BYTES;
        mma_tile(acc, As, As + 128 * STRIDE, wm, wn, lrow, lcol);
        __syncthreads();
    }

    // --- scatter epilogue ---
    const int grow0 = bm * BMt + wm + (lane >> 2);
    const int gcol0 = bn * BNt + wn + (lane & 3) * 2;
#pragma unroll
    for (int mf = 0; mf < 4; mf++) {
#pragma unroll
        for (int h = 0; h < 2; h++) {
            const int r = grow0 + mf * 16 + h * 8;
#pragma unroll
            for (int nf = 0; nf < 4; nf++) {
                const int col = gcol0 + nf * 8;
#pragma unroll
                for (int j = 0; j < 2; j++) {
                    const int c = col + j;
                    float val = acc[mf][nf][h * 2 + j] + g_b2[c];
                    if (c < N_DIM) {
                        out[OFF_MU + (size_t)r * N_DIM + c] = val;
                    } else if (c < 2 * N_DIM) {
                        out[OFF_FB + (size_t)r * N_DIM + (c - N_DIM)] = val;
                    } else if (c == 2 * N_DIM) {
                        float sp = fmaxf(val, 0.0f) + log1pf(expf(-fabsf(val)));
                        out[OFF_PI + r] = fminf(sp, 10.0f);
                    }
                }
            }
        }
    }
}

// ---------------------------------------------------------------------------
// Borderline refinement: recompute flagged drives exactly in fp64 (one warp
// per element). Overwrites v, z, x, b AND patches g_x16.
// ---------------------------------------------------------------------------
__global__ void refine_kernel(const float* __restrict__ x_l4, const float* __restrict__ x_l23,
                              const float* __restrict__ cue, const float* __restrict__ task,
                              const float* __restrict__ v_prev, const float* __restrict__ z_prev,
                              const float* __restrict__ x_prev, const float* __restrict__ b_prev,
                              const float* __restrict__ adapt_mask,
                              const float* __restrict__ W_in, const float* __restrict__ b_in,
                              const float* __restrict__ W_rec,
                              float* __restrict__ out) {
    int nitems = g_cnt < MAXB ? g_cnt : MAXB;
    int warp = (blockIdx.x * blockDim.x + threadIdx.x) >> 5;
    int lane = threadIdx.x & 31;
    int nwarps = (gridDim.x * blockDim.x) >> 5;
    for (int i = warp; i < nitems; i += nwarps) {
        int2 rc = g_list[i];
        double s = 0.0;
        for (int k = lane; k < KACT; k += 32) {
            float a = a_elem(rc.x, k, x_l4, x_l23, cue, task, x_prev);
            float w = w_elem(rc.y, k, W_in, W_rec);
            s += (double)a * (double)w;
        }
#pragma unroll
        for (int o = 16; o > 0; o >>= 1)
            s += __shfl_xor_sync(0xffffffffu, s, o);
        if (lane == 0) {
            size_t idx = (size_t)rc.x * NV2 + rc.y;
            double drive = s + (double)b_in[rc.y];
            double vd = (double)BETA_MEM * (double)v_prev[idx] + drive - (double)z_prev[idx];
            float bp = b_prev[idx];
            float Bth = fmaf(BETA_AD, bp, 1.0f);
            float z = (vd - (double)Bth) > 0.0 ? 1.0f : 0.0f;
            float xn = ALPHA_F * x_prev[idx] + z;
            out[OFF_V + idx] = (float)vd;
            out[OFF_Z + idx] = z;
            out[OFF_X + idx] = xn;
            out[OFF_B + idx] = (RHO_AD * bp + ONE_M_RHO * z) * adapt_mask[rc.y];
            g_x16[idx] = __float2half_rn(xn);
        }
    }
}

// ---------------------------------------------------------------------------
// Softmax over [B, 180] in place (one warp per row)
// ---------------------------------------------------------------------------
__global__ void softmax_kernel(float* __restrict__ out) {
    int warp = (blockIdx.x * blockDim.x + threadIdx.x) >> 5;
    int lane = threadIdx.x & 31;
    if (warp >= B_DIM) return;
    float* row = out + OFF_MU + (size_t)warp * N_DIM;

    float vals[6];
    float mx = -1e30f;
#pragma unroll
    for (int t = 0; t < 6; t++) {
        int j = lane + t * 32;
        vals[t] = (j < N_DIM) ? row[j] : -1e30f;
        mx = fmaxf(mx, vals[t]);
    }
#pragma unroll
    for (int o = 16; o > 0; o >>= 1) mx = fmaxf(mx, __shfl_xor_sync(0xffffffffu, mx, o));
    float s = 0.0f;
#pragma unroll
    for (int t = 0; t < 6; t++) {
        int j = lane + t * 32;
        float e = expf(vals[t] - mx);
        vals[t] = e;
        if (j < N_DIM) s += e;
    }
#pragma unroll
    for (int o = 16; o > 0; o >>= 1) s += __shfl_xor_sync(0xffffffffu, s, o);
    float inv = 1.0f / s;
#pragma unroll
    for (int t = 0; t < 6; t++) {
        int j = lane + t * 32;
        if (j < N_DIM) row[j] = vals[t] * inv;
    }
}

// ---------------------------------------------------------------------------
// Launch (capture slot #4 = refine_kernel this round)
// ---------------------------------------------------------------------------
extern "C" void kernel_launch(void* const* d_in, const int* in_sizes, int n_in,
                              void* d_out, int out_size) {
    const float* x_l4   = (const float*)d_in[0];
    const float* x_l23  = (const float*)d_in[1];
    const float* cue    = (const float*)d_in[2];
    const float* task   = (const float*)d_in[3];
    const float* v_prev = (const float*)d_in[4];
    const float* z_prev = (const float*)d_in[5];
    const float* x_prev = (const float*)d_in[6];
    const float* b_prev = (const float*)d_in[7];
    const float* amask  = (const float*)d_in[8];
    const float* W_in   = (const float*)d_in[9];
    const float* b_in   = (const float*)d_in[10];
    const float* W_rec  = (const float*)d_in[11];
    const float* W_mu   = (const float*)d_in[12];
    const float* b_mu   = (const float*)d_in[13];
    const float* W_fb   = (const float*)d_in[14];
    const float* b_fb   = (const float*)d_in[15];
    const float* W_pi   = (const float*)d_in[16];
    const float* b_pi   = (const float*)d_in[17];
    float* out = (float*)d_out;

    cudaFuncSetAttribute(gemm1_mma, cudaFuncAttributeMaxDynamicSharedMemorySize, SMEM_DYN);
    cudaFuncSetAttribute(gemm2_mma, cudaFuncAttributeMaxDynamicSharedMemorySize, SMEM_DYN);

    pack_AW_kernel<<<dim3((KP + 1023) / 1024, 2 * B_DIM), 256>>>(
        x_l4, x_l23, cue, task, x_prev, W_in, W_rec);                       // 1
    pack_W2_kernel<<<dim3((K2 + 1023) / 1024, N2PAD), 256>>>(
        W_mu, b_mu, W_fb, b_fb, W_pi, b_pi);                                // 2
    gemm1_mma<<<dim3(NV2 / BNt, B_DIM / BMt), 256, SMEM_DYN>>>(
        v_prev, z_prev, x_prev, b_prev, amask, b_in, out);                  // 3
    refine_kernel<<<128, 256>>>(x_l4, x_l23, cue, task, v_prev, z_prev,
                                x_prev, b_prev, amask, W_in, b_in, W_rec, out); // 4 (profiled)
    gemm2_mma<<<dim3(N2PAD / BNt, B_DIM / BMt), 256, SMEM_DYN>>>(out);      // 5
    softmax_kernel<<<(B_DIM * 32 + 255) / 256, 256>>>(out);                 // 6
}

// round 16
// speedup vs baseline: 4.4676x; 1.2470x over previous
#include <cuda_runtime.h>
#include <cuda_fp16.h>
#include <math.h>
#include <stdint.h>

// ---------------------------------------------------------------------------
// Problem constants
// ---------------------------------------------------------------------------
#define B_DIM   4096
#define N_DIM   180
#define NV2     4096
#define IN_DIM  542            // 3*N + 2
#define KACT    4638           // actual K of [inputs | x_prev]
#define K2      4096
#define N2PAD   384            // 180 + 180 + 1 padded to multiple of 128

// single-term fp16 GEMM-1 layout
#define KP      4672           // K padded to multiple of 64
#define BKt     64             // fp16 elems per k-tile
#define NT_G1   (KP / BKt)     // 73 k-tiles

// 2-term fp16 GEMM-2 layout (x single, W2 split hi/lo): K tiles = 2 * 64
#define NT_G2   128

// Output layout (tuple flattened in return order, all fp32)
#define OFF_MU  0
#define OFF_PI  737280
#define OFF_FB  741376
#define OFF_V   1478656
#define OFF_Z   18255872
#define OFF_X   35033088
#define OFF_B   51810304

#define BETA_MEM   0.95122942450071400910f   // exp(-1/20)
#define RHO_AD     0.99501247919268232265f   // exp(-1/200)
#define ONE_M_RHO  0.00498752080731767735f
#define BETA_AD    1.8f
#define ALPHA_F    0.9f

#define TAU_BORDER 1e-3f       // |v - B_thresh| band (≈6.5 sigma of fp16 GEMM error)
#define MAXB       65536

// ---------------------------------------------------------------------------
// Scratch (static device globals -- ~117 MB total, inside proven envelope)
// ---------------------------------------------------------------------------
__device__ __half g_A16[(size_t)B_DIM * KP];    // 38.3 MB
__device__ __half g_W16[(size_t)NV2 * KP];      // 38.3 MB
__device__ __half g_x16[(size_t)B_DIM * K2];    // 33.6 MB (stage-2 A operand)
__device__ __half g_W2h[(size_t)N2PAD * K2];    // 3 MB
__device__ __half g_W2l[(size_t)N2PAD * K2];    // 3 MB
__device__ float g_b2[N2PAD];
__device__ int   g_cnt;
__device__ int2  g_list[MAXB];

// ---------------------------------------------------------------------------
// PTX helpers (base-ISA only: cp.async, ldmatrix, mma.sync -- all sm_80+)
// ---------------------------------------------------------------------------
__device__ __forceinline__ uint32_t smem_u32(const void* p) {
    uint32_t a;
    asm("{ .reg .u64 t; cvta.to.shared.u64 t, %1; cvt.u32.u64 %0, t; }" : "=r"(a) : "l"(p));
    return a;
}
__device__ __forceinline__ void cp_async16(uint32_t saddr, const void* gaddr) {
    asm volatile("cp.async.cg.shared.global [%0], [%1], 16;" :: "r"(saddr), "l"(gaddr) : "memory");
}
#define CP_COMMIT() asm volatile("cp.async.commit_group;" ::: "memory")
#define CP_WAIT0()  asm volatile("cp.async.wait_group 0;" ::: "memory")
#define CP_WAIT1()  asm volatile("cp.async.wait_group 1;" ::: "memory")

__device__ __forceinline__ void ldm_x4(uint32_t& r0, uint32_t& r1, uint32_t& r2, uint32_t& r3,
                                       uint32_t addr) {
    asm volatile("ldmatrix.sync.aligned.m8n8.x4.shared.b16 {%0,%1,%2,%3}, [%4];"
                 : "=r"(r0), "=r"(r1), "=r"(r2), "=r"(r3) : "r"(addr));
}
__device__ __forceinline__ void mma_f16(float& c0, float& c1, float& c2, float& c3,
                                        uint32_t a0, uint32_t a1, uint32_t a2, uint32_t a3,
                                        uint32_t b0, uint32_t b1) {
    asm volatile("mma.sync.aligned.m16n8k16.row.col.f32.f16.f16.f32 "
                 "{%0,%1,%2,%3}, {%4,%5,%6,%7}, {%8,%9}, {%0,%1,%2,%3};"
                 : "+f"(c0), "+f"(c1), "+f"(c2), "+f"(c3)
                 : "r"(a0), "r"(a1), "r"(a2), "r"(a3), "r"(b0), "r"(b1));
}

// ---------------------------------------------------------------------------
// Piecewise input accessors (k in [0, KACT))
// ---------------------------------------------------------------------------
__device__ __forceinline__ float a_elem(int b, int k,
        const float* x_l4, const float* x_l23, const float* cue,
        const float* task, const float* x_prev) {
    if (k < N_DIM)            return x_l4[b * N_DIM + k];
    if (k < 2 * N_DIM)        return x_l23[b * N_DIM + (k - N_DIM)];
    if (k < 3 * N_DIM)        return cue[b * N_DIM + (k - 2 * N_DIM)];
    if (k < IN_DIM)           return task[b * 2 + (k - 3 * N_DIM)];
    return x_prev[(size_t)b * NV2 + (k - IN_DIM)];
}
__device__ __forceinline__ float w_elem(int n, int k,
        const float* W_in, const float* W_rec) {
    if (k < IN_DIM) return W_in[(size_t)n * IN_DIM + k];
    return W_rec[(size_t)n * NV2 + (k - IN_DIM)];
}

// ---------------------------------------------------------------------------
// Pack kernels (MLP-4 per thread, uniform per-block A/W branch)
//   grid.y row in [0, 8192): row < 4096 -> A row b; else W row n = row - 4096.
//   Also zeroes g_cnt (runs before gemm1).
// ---------------------------------------------------------------------------
__global__ void pack_AW_kernel(const float* __restrict__ x_l4,
                               const float* __restrict__ x_l23,
                               const float* __restrict__ cue,
                               const float* __restrict__ task,
                               const float* __restrict__ x_prev,
                               const float* __restrict__ W_in,
                               const float* __restrict__ W_rec) {
    const int row = blockIdx.y;
    const int k0 = blockIdx.x * 1024 + threadIdx.x;
    if (row == 0 && k0 == 0) g_cnt = 0;
    if (row < B_DIM) {
        float v[4];
#pragma unroll
        for (int i = 0; i < 4; i++) {
            int k = k0 + i * 256;
            v[i] = (k < KACT) ? a_elem(row, k, x_l4, x_l23, cue, task, x_prev) : 0.0f;
        }
#pragma unroll
        for (int i = 0; i < 4; i++) {
            int k = k0 + i * 256;
            if (k < KP) g_A16[(size_t)row * KP + k] = __float2half_rn(v[i]);
        }
    } else {
        const int n = row - B_DIM;
        float v[4];
#pragma unroll
        for (int i = 0; i < 4; i++) {
            int k = k0 + i * 256;
            v[i] = (k < KACT) ? w_elem(n, k, W_in, W_rec) : 0.0f;
        }
#pragma unroll
        for (int i = 0; i < 4; i++) {
            int k = k0 + i * 256;
            if (k < KP) g_W16[(size_t)n * KP + k] = __float2half_rn(v[i]);
        }
    }
}

// W2 rows (mu | fb | pi | pad) -> fp16 hi/lo split + fp32 bias (MLP-4)
__global__ void pack_W2_kernel(const float* __restrict__ W_mu, const float* __restrict__ b_mu,
                               const float* __restrict__ W_fb, const float* __restrict__ b_fb,
                               const float* __restrict__ W_pi, const float* __restrict__ b_pi) {
    const int r = blockIdx.y;
    const int k0 = blockIdx.x * 1024 + threadIdx.x;
    const float* src = (r < N_DIM) ? (W_mu + (size_t)r * K2)
                     : (r < 2 * N_DIM) ? (W_fb + (size_t)(r - N_DIM) * K2)
                     : (r == 2 * N_DIM) ? W_pi : nullptr;
    float v[4];
#pragma unroll
    for (int i = 0; i < 4; i++) {
        int k = k0 + i * 256;
        v[i] = (src && k < K2) ? src[k] : 0.0f;
    }
#pragma unroll
    for (int i = 0; i < 4; i++) {
        int k = k0 + i * 256;
        if (k < K2) {
            __half hi = __float2half_rn(v[i]);
            __half lo = __float2half_rn(v[i] - __half2float(hi));
            g_W2h[(size_t)r * K2 + k] = hi;
            g_W2l[(size_t)r * K2 + k] = lo;
        }
    }
    if (k0 == 0) {
        float bb = 0.0f;
        if (r < N_DIM)           bb = b_mu[r];
        else if (r < 2 * N_DIM)  bb = b_fb[r - N_DIM];
        else if (r == 2 * N_DIM) bb = b_pi[0];
        g_b2[r] = bb;
    }
}

// ---------------------------------------------------------------------------
// Shared GEMM geometry: CTA 128x128, BK=64, 2-stage cp.async, 8 warps (2m x 4n)
// ---------------------------------------------------------------------------
#define BMt 128
#define BNt 128
#define STRIDE 144                       // bytes per smem row (128 data + 16 pad)
#define STAGE_BYTES (256 * STRIDE)       // 36864 (A: rows 0-127, B: rows 128-255)
#define STAGES 2
#define SMEM_DYN (STAGES * STAGE_BYTES)  // 73728

__device__ __forceinline__ void load_tile(uint32_t s, const __half* Abase, const __half* Bbase,
                                          size_t a_kstride, size_t b_kstride,
                                          int arow0, int brow0, size_t akoff, size_t bkoff,
                                          int tid) {
#pragma unroll
    for (int i = 0; i < 4; i++) {                     // A: 128 rows x 8 chunks
        int idx = tid + i * 256;
        int row = idx >> 3, ch = idx & 7;
        const char* g = (const char*)Abase
            + ((size_t)(arow0 + row) * a_kstride + akoff) * 2 + ch * 16;
        cp_async16(s + row * STRIDE + ch * 16, g);
    }
#pragma unroll
    for (int i = 0; i < 4; i++) {                     // B: 128 rows x 8 chunks
        int idx = tid + i * 256;
        int row = idx >> 3, ch = idx & 7;
        const char* g = (const char*)Bbase
            + ((size_t)(brow0 + row) * b_kstride + bkoff) * 2 + ch * 16;
        cp_async16(s + (128 + row) * STRIDE + ch * 16, g);
    }
}

// Compute one 64-wide k-tile from smem stage into acc
__device__ __forceinline__ void mma_tile(float (&acc)[4][4][4], uint32_t As, uint32_t Bs,
                                         int wm, int wn, int lrow, int lcol) {
#pragma unroll
    for (int ks = 0; ks < 4; ks++) {
        const uint32_t coff = (ks * 16 + lcol) * 2;
        uint32_t a[4][4];
#pragma unroll
        for (int mf = 0; mf < 4; mf++)
            ldm_x4(a[mf][0], a[mf][1], a[mf][2], a[mf][3],
                   As + (wm + mf * 16 + lrow) * STRIDE + coff);
        uint32_t b[2][4];
#pragma unroll
        for (int nt = 0; nt < 2; nt++)
            ldm_x4(b[nt][0], b[nt][1], b[nt][2], b[nt][3],
                   Bs + (wn + nt * 16 + lrow) * STRIDE + coff);
#pragma unroll
        for (int mf = 0; mf < 4; mf++)
#pragma unroll
            for (int nf = 0; nf < 4; nf++) {
                const int nt = nf >> 1, hi = nf & 1;
                mma_f16(acc[mf][nf][0], acc[mf][nf][1], acc[mf][nf][2], acc[mf][nf][3],
                        a[mf][0], a[mf][1], a[mf][2], a[mf][3],
                        b[nt][hi], b[nt][2 + hi]);
            }
    }
}

// ---------------------------------------------------------------------------
// GEMM 1 (mma.sync fp16): drive = A16 @ W16^T + b_in, fused spiking epilogue.
//   Epilogue also emits x as fp16 into g_x16 (stage-2 operand).
// ---------------------------------------------------------------------------
__global__ __launch_bounds__(256, 2)
void gemm1_mma(const float* __restrict__ v_prev, const float* __restrict__ z_prev,
               const float* __restrict__ x_prev, const float* __restrict__ b_prev,
               const float* __restrict__ adapt_mask, const float* __restrict__ b_in,
               float* __restrict__ out) {
    extern __shared__ __align__(256) char smem[];
    const uint32_t sb = smem_u32(smem);
    const int tid = threadIdx.x, wid = tid >> 5, lane = tid & 31;
    const int bn = blockIdx.x, bm = blockIdx.y;
    const int wm = (wid & 1) * 64;
    const int wn = (wid >> 1) * 32;
    const int lrow = lane & 15;
    const int lcol = ((lane >> 4) & 1) * 8;

    float acc[4][4][4];
#pragma unroll
    for (int i = 0; i < 4; i++)
#pragma unroll
        for (int j = 0; j < 4; j++)
#pragma unroll
            for (int q = 0; q < 4; q++) acc[i][j][q] = 0.0f;

    load_tile(sb, g_A16, g_W16, KP, KP, bm * BMt, bn * BNt, 0, 0, tid);
    CP_COMMIT();

    for (int t = 0; t < NT_G1; t++) {
        if (t + 1 < NT_G1) {
            load_tile(sb + ((t + 1) & 1) * STAGE_BYTES, g_A16, g_W16, KP, KP,
                      bm * BMt, bn * BNt, (size_t)(t + 1) * BKt, (size_t)(t + 1) * BKt, tid);
            CP_COMMIT();
            CP_WAIT1();
        } else {
            CP_WAIT0();
        }
        __syncthreads();
        const uint32_t As = sb + (t & 1) * STAGE_BYTES;
        mma_tile(acc, As, As + 128 * STRIDE, wm, wn, lrow, lcol);
        __syncthreads();
    }

    // --- fused spiking epilogue from fragments ---
    const int grow0 = bm * BMt + wm + (lane >> 2);
    const int gcol0 = bn * BNt + wn + (lane & 3) * 2;
#pragma unroll
    for (int mf = 0; mf < 4; mf++) {
#pragma unroll
        for (int h = 0; h < 2; h++) {
            const int row = grow0 + mf * 16 + h * 8;
#pragma unroll
            for (int nf = 0; nf < 4; nf++) {
                const int col = gcol0 + nf * 8;
                const size_t o = (size_t)row * NV2 + col;
                float2 bi = *(const float2*)(b_in + col);
                float2 am = *(const float2*)(adapt_mask + col);
                float2 vp = *(const float2*)(v_prev + o);
                float2 zp = *(const float2*)(z_prev + o);
                float2 bp = *(const float2*)(b_prev + o);
                float2 xp = *(const float2*)(x_prev + o);
                float d[2] = { acc[mf][nf][h * 2 + 0], acc[mf][nf][h * 2 + 1] };
                float vo[2], zo[2], xo[2], bo[2];
#pragma unroll
                for (int j = 0; j < 2; j++) {
                    float drive = d[j] + ((const float*)&bi)[j];
                    float v = BETA_MEM * ((const float*)&vp)[j] + drive - ((const float*)&zp)[j];
                    float Bth = fmaf(BETA_AD, ((const float*)&bp)[j], 1.0f);
                    float u = v - Bth;
                    float z = u > 0.0f ? 1.0f : 0.0f;
                    if (fabsf(u) < TAU_BORDER) {
                        int idx = atomicAdd(&g_cnt, 1);
                        if (idx < MAXB) g_list[idx] = make_int2(row, col + j);
                    }
                    vo[j] = v; zo[j] = z;
                    bo[j] = (RHO_AD * ((const float*)&bp)[j] + ONE_M_RHO * z) * ((const float*)&am)[j];
                    xo[j] = ALPHA_F * ((const float*)&xp)[j] + z;
                }
                *(float2*)(out + OFF_V + o) = make_float2(vo[0], vo[1]);
                *(float2*)(out + OFF_Z + o) = make_float2(zo[0], zo[1]);
                *(float2*)(out + OFF_X + o) = make_float2(xo[0], xo[1]);
                *(float2*)(out + OFF_B + o) = make_float2(bo[0], bo[1]);
                *(__half2*)(g_x16 + o) = __floats2half2_rn(xo[0], xo[1]);
            }
        }
    }
}

// ---------------------------------------------------------------------------
// GEMM 2 (mma.sync fp16, 2-term W-split): logits = x @ (W2h + W2l)^T + b2
// ---------------------------------------------------------------------------
__global__ __launch_bounds__(256, 2)
void gemm2_mma(float* __restrict__ out) {
    extern __shared__ __align__(256) char smem[];
    const uint32_t sb = smem_u32(smem);
    const int tid = threadIdx.x, wid = tid >> 5, lane = tid & 31;
    const int bn = blockIdx.x, bm = blockIdx.y;
    const int wm = (wid & 1) * 64;
    const int wn = (wid >> 1) * 32;
    const int lrow = lane & 15;
    const int lcol = ((lane >> 4) & 1) * 8;

    float acc[4][4][4];
#pragma unroll
    for (int i = 0; i < 4; i++)
#pragma unroll
        for (int j = 0; j < 4; j++)
#pragma unroll
            for (int q = 0; q < 4; q++) acc[i][j][q] = 0.0f;

    load_tile(sb, g_x16, g_W2h, K2, K2, bm * BMt, bn * BNt, 0, 0, tid);
    CP_COMMIT();

    for (int t = 0; t < NT_G2; t++) {
        if (t + 1 < NT_G2) {
            const int tn = t + 1;
            const __half* Wb = (tn >> 6) ? g_W2l : g_W2h;
            load_tile(sb + (tn & 1) * STAGE_BYTES, g_x16, Wb, K2, K2,
                      bm * BMt, bn * BNt,
                      (size_t)(tn & 63) * BKt, (size_t)(tn & 63) * BKt, tid);
            CP_COMMIT();
            CP_WAIT1();
        } else {
            CP_WAIT0();
        }
        __syncthreads();
        const uint32_t As = sb + (t & 1) * STAGE_BYTES;
        mma_tile(acc, As, As + 128 * STRIDE, wm, wn, lrow, lcol);
        __syncthreads();
    }

    // --- scatter epilogue ---
    const int grow0 = bm * BMt + wm + (lane >> 2);
    const int gcol0 = bn * BNt + wn + (lane & 3) * 2;
#pragma unroll
    for (int mf = 0; mf < 4; mf++) {
#pragma unroll
        for (int h = 0; h < 2; h++) {
            const int r = grow0 + mf * 16 + h * 8;
#pragma unroll
            for (int nf = 0; nf < 4; nf++) {
                const int col = gcol0 + nf * 8;
#pragma unroll
                for (int j = 0; j < 2; j++) {
                    const int c = col + j;
                    float val = acc[mf][nf][h * 2 + j] + g_b2[c];
                    if (c < N_DIM) {
                        out[OFF_MU + (size_t)r * N_DIM + c] = val;
                    } else if (c < 2 * N_DIM) {
                        out[OFF_FB + (size_t)r * N_DIM + (c - N_DIM)] = val;
                    } else if (c == 2 * N_DIM) {
                        float sp = fmaxf(val, 0.0f) + log1pf(expf(-fabsf(val)));
                        out[OFF_PI + r] = fminf(sp, 10.0f);
                    }
                }
            }
        }
    }
}

// ---------------------------------------------------------------------------
// Borderline refinement (MLP-4): recompute flagged drives exactly in fp64.
//   4 independent double accumulators + 8 loads in flight per warp; 512 blocks.
//   Overwrites v, z, x, b AND patches g_x16.
// ---------------------------------------------------------------------------
__global__ void refine_kernel(const float* __restrict__ x_l4, const float* __restrict__ x_l23,
                              const float* __restrict__ cue, const float* __restrict__ task,
                              const float* __restrict__ v_prev, const float* __restrict__ z_prev,
                              const float* __restrict__ x_prev, const float* __restrict__ b_prev,
                              const float* __restrict__ adapt_mask,
                              const float* __restrict__ W_in, const float* __restrict__ b_in,
                              const float* __restrict__ W_rec,
                              float* __restrict__ out) {
    int nitems = g_cnt < MAXB ? g_cnt : MAXB;
    int warp = (blockIdx.x * blockDim.x + threadIdx.x) >> 5;
    int lane = threadIdx.x & 31;
    int nwarps = (gridDim.x * blockDim.x) >> 5;
    for (int i = warp; i < nitems; i += nwarps) {
        int2 rc = g_list[i];
        double s0 = 0.0, s1 = 0.0, s2 = 0.0, s3 = 0.0;
        for (int kb = 0; kb < KACT; kb += 128) {
            const int k0 = kb + lane;
            float a0 = 0.f, a1 = 0.f, a2 = 0.f, a3 = 0.f;
            float w0 = 0.f, w1 = 0.f, w2 = 0.f, w3 = 0.f;
            if (k0 < KACT)      { a0 = a_elem(rc.x, k0,      x_l4, x_l23, cue, task, x_prev);
                                  w0 = w_elem(rc.y, k0,      W_in, W_rec); }
            if (k0 + 32 < KACT) { a1 = a_elem(rc.x, k0 + 32, x_l4, x_l23, cue, task, x_prev);
                                  w1 = w_elem(rc.y, k0 + 32, W_in, W_rec); }
            if (k0 + 64 < KACT) { a2 = a_elem(rc.x, k0 + 64, x_l4, x_l23, cue, task, x_prev);
                                  w2 = w_elem(rc.y, k0 + 64, W_in, W_rec); }
            if (k0 + 96 < KACT) { a3 = a_elem(rc.x, k0 + 96, x_l4, x_l23, cue, task, x_prev);
                                  w3 = w_elem(rc.y, k0 + 96, W_in, W_rec); }
            s0 += (double)a0 * (double)w0;
            s1 += (double)a1 * (double)w1;
            s2 += (double)a2 * (double)w2;
            s3 += (double)a3 * (double)w3;
        }
        double s = (s0 + s1) + (s2 + s3);
#pragma unroll
        for (int o = 16; o > 0; o >>= 1)
            s += __shfl_xor_sync(0xffffffffu, s, o);
        if (lane == 0) {
            size_t idx = (size_t)rc.x * NV2 + rc.y;
            double drive = s + (double)b_in[rc.y];
            double vd = (double)BETA_MEM * (double)v_prev[idx] + drive - (double)z_prev[idx];
            float bp = b_prev[idx];
            float Bth = fmaf(BETA_AD, bp, 1.0f);
            float z = (vd - (double)Bth) > 0.0 ? 1.0f : 0.0f;
            float xn = ALPHA_F * x_prev[idx] + z;
            out[OFF_V + idx] = (float)vd;
            out[OFF_Z + idx] = z;
            out[OFF_X + idx] = xn;
            out[OFF_B + idx] = (RHO_AD * bp + ONE_M_RHO * z) * adapt_mask[rc.y];
            g_x16[idx] = __float2half_rn(xn);
        }
    }
}

// ---------------------------------------------------------------------------
// Softmax over [B, 180] in place (one warp per row)
// ---------------------------------------------------------------------------
__global__ void softmax_kernel(float* __restrict__ out) {
    int warp = (blockIdx.x * blockDim.x + threadIdx.x) >> 5;
    int lane = threadIdx.x & 31;
    if (warp >= B_DIM) return;
    float* row = out + OFF_MU + (size_t)warp * N_DIM;

    float vals[6];
    float mx = -1e30f;
#pragma unroll
    for (int t = 0; t < 6; t++) {
        int j = lane + t * 32;
        vals[t] = (j < N_DIM) ? row[j] : -1e30f;
        mx = fmaxf(mx, vals[t]);
    }
#pragma unroll
    for (int o = 16; o > 0; o >>= 1) mx = fmaxf(mx, __shfl_xor_sync(0xffffffffu, mx, o));
    float s = 0.0f;
#pragma unroll
    for (int t = 0; t < 6; t++) {
        int j = lane + t * 32;
        float e = expf(vals[t] - mx);
        vals[t] = e;
        if (j < N_DIM) s += e;
    }
#pragma unroll
    for (int o = 16; o > 0; o >>= 1) s += __shfl_xor_sync(0xffffffffu, s, o);
    float inv = 1.0f / s;
#pragma unroll
    for (int t = 0; t < 6; t++) {
        int j = lane + t * 32;
        if (j < N_DIM) row[j] = vals[t] * inv;
    }
}

// ---------------------------------------------------------------------------
// Launch (capture slot #4 = refine_kernel -- verifies this round's fix)
// ---------------------------------------------------------------------------
extern "C" void kernel_launch(void* const* d_in, const int* in_sizes, int n_in,
                              void* d_out, int out_size) {
    const float* x_l4   = (const float*)d_in[0];
    const float* x_l23  = (const float*)d_in[1];
    const float* cue    = (const float*)d_in[2];
    const float* task   = (const float*)d_in[3];
    const float* v_prev = (const float*)d_in[4];
    const float* z_prev = (const float*)d_in[5];
    const float* x_prev = (const float*)d_in[6];
    const float* b_prev = (const float*)d_in[7];
    const float* amask  = (const float*)d_in[8];
    const float* W_in   = (const float*)d_in[9];
    const float* b_in   = (const float*)d_in[10];
    const float* W_rec  = (const float*)d_in[11];
    const float* W_mu   = (const float*)d_in[12];
    const float* b_mu   = (const float*)d_in[13];
    const float* W_fb   = (const float*)d_in[14];
    const float* b_fb   = (const float*)d_in[15];
    const float* W_pi   = (const float*)d_in[16];
    const float* b_pi   = (const float*)d_in[17];
    float* out = (float*)d_out;

    cudaFuncSetAttribute(gemm1_mma, cudaFuncAttributeMaxDynamicSharedMemorySize, SMEM_DYN);
    cudaFuncSetAttribute(gemm2_mma, cudaFuncAttributeMaxDynamicSharedMemorySize, SMEM_DYN);

    pack_AW_kernel<<<dim3((KP + 1023) / 1024, 2 * B_DIM), 256>>>(
        x_l4, x_l23, cue, task, x_prev, W_in, W_rec);                       // 1
    pack_W2_kernel<<<dim3((K2 + 1023) / 1024, N2PAD), 256>>>(
        W_mu, b_mu, W_fb, b_fb, W_pi, b_pi);                                // 2
    gemm1_mma<<<dim3(NV2 / BNt, B_DIM / BMt), 256, SMEM_DYN>>>(
        v_prev, z_prev, x_prev, b_prev, amask, b_in, out);                  // 3
    refine_kernel<<<512, 256>>>(x_l4, x_l23, cue, task, v_prev, z_prev,
                                x_prev, b_prev, amask, W_in, b_in, W_rec, out); // 4 (profiled)
    gemm2_mma<<<dim3(N2PAD / BNt, B_DIM / BMt), 256, SMEM_DYN>>>(out);      // 5
    softmax_kernel<<<(B_DIM * 32 + 255) / 256, 256>>>(out);                 // 6
}

// round 17
// speedup vs baseline: 4.6634x; 1.0438x over previous
#include <cuda_runtime.h>
#include <cuda_fp16.h>
#include <math.h>
#include <stdint.h>

// ---------------------------------------------------------------------------
// Problem constants
// ---------------------------------------------------------------------------
#define B_DIM   4096
#define N_DIM   180
#define NV2     4096
#define IN_DIM  542            // 3*N + 2
#define KACT    4638           // actual K of [inputs | x_prev]
#define K2      4096
#define N2PAD   384            // 180 + 180 + 1 padded to multiple of 128

// single-term fp16 GEMM-1 layout
#define KP      4672           // K padded to multiple of 64
#define BKt     64             // fp16 elems per k-tile
#define NT_G1   (KP / BKt)     // 73 k-tiles

// 2-term fp16 GEMM-2 layout (x single, W2 split hi/lo): K tiles = 2 * 64
#define NT_G2   128

// Output layout (tuple flattened in return order, all fp32)
#define OFF_MU  0
#define OFF_PI  737280
#define OFF_FB  741376
#define OFF_V   1478656
#define OFF_Z   18255872
#define OFF_X   35033088
#define OFF_B   51810304

#define BETA_MEM   0.95122942450071400910f   // exp(-1/20)
#define RHO_AD     0.99501247919268232265f   // exp(-1/200)
#define ONE_M_RHO  0.00498752080731767735f
#define BETA_AD    1.8f
#define ALPHA_F    0.9f

#define TAU_BORDER 1e-3f       // |v - B_thresh| band (≈6.5 sigma of fp16 GEMM error)
#define MAXB       65536

// ---------------------------------------------------------------------------
// Scratch (static device globals -- ~117 MB total, inside proven envelope)
// ---------------------------------------------------------------------------
__device__ __half g_A16[(size_t)B_DIM * KP];    // 38.3 MB
__device__ __half g_W16[(size_t)NV2 * KP];      // 38.3 MB
__device__ __half g_x16[(size_t)B_DIM * K2];    // 33.6 MB (stage-2 A operand)
__device__ __half g_W2h[(size_t)N2PAD * K2];    // 3 MB
__device__ __half g_W2l[(size_t)N2PAD * K2];    // 3 MB
__device__ float g_b2[N2PAD];
__device__ int   g_cnt;
__device__ int2  g_list[MAXB];

// ---------------------------------------------------------------------------
// PTX helpers (base-ISA only: cp.async, ldmatrix, mma.sync -- all sm_80+)
// ---------------------------------------------------------------------------
__device__ __forceinline__ uint32_t smem_u32(const void* p) {
    uint32_t a;
    asm("{ .reg .u64 t; cvta.to.shared.u64 t, %1; cvt.u32.u64 %0, t; }" : "=r"(a) : "l"(p));
    return a;
}
__device__ __forceinline__ void cp_async16(uint32_t saddr, const void* gaddr) {
    asm volatile("cp.async.cg.shared.global [%0], [%1], 16;" :: "r"(saddr), "l"(gaddr) : "memory");
}
#define CP_COMMIT() asm volatile("cp.async.commit_group;" ::: "memory")
#define CP_WAIT0()  asm volatile("cp.async.wait_group 0;" ::: "memory")
#define CP_WAIT1()  asm volatile("cp.async.wait_group 1;" ::: "memory")

__device__ __forceinline__ void ldm_x4(uint32_t& r0, uint32_t& r1, uint32_t& r2, uint32_t& r3,
                                       uint32_t addr) {
    asm volatile("ldmatrix.sync.aligned.m8n8.x4.shared.b16 {%0,%1,%2,%3}, [%4];"
                 : "=r"(r0), "=r"(r1), "=r"(r2), "=r"(r3) : "r"(addr));
}
__device__ __forceinline__ void mma_f16(float& c0, float& c1, float& c2, float& c3,
                                        uint32_t a0, uint32_t a1, uint32_t a2, uint32_t a3,
                                        uint32_t b0, uint32_t b1) {
    asm volatile("mma.sync.aligned.m16n8k16.row.col.f32.f16.f16.f32 "
                 "{%0,%1,%2,%3}, {%4,%5,%6,%7}, {%8,%9}, {%0,%1,%2,%3};"
                 : "+f"(c0), "+f"(c1), "+f"(c2), "+f"(c3)
                 : "r"(a0), "r"(a1), "r"(a2), "r"(a3), "r"(b0), "r"(b1));
}

// ---------------------------------------------------------------------------
// Piecewise input accessors (k in [0, KACT))
// ---------------------------------------------------------------------------
__device__ __forceinline__ float a_elem(int b, int k,
        const float* x_l4, const float* x_l23, const float* cue,
        const float* task, const float* x_prev) {
    if (k < N_DIM)            return x_l4[b * N_DIM + k];
    if (k < 2 * N_DIM)        return x_l23[b * N_DIM + (k - N_DIM)];
    if (k < 3 * N_DIM)        return cue[b * N_DIM + (k - 2 * N_DIM)];
    if (k < IN_DIM)           return task[b * 2 + (k - 3 * N_DIM)];
    return x_prev[(size_t)b * NV2 + (k - IN_DIM)];
}
__device__ __forceinline__ float w_elem(int n, int k,
        const float* W_in, const float* W_rec) {
    if (k < IN_DIM) return W_in[(size_t)n * IN_DIM + k];
    return W_rec[(size_t)n * NV2 + (k - IN_DIM)];
}

// ---------------------------------------------------------------------------
// Pack kernels (MLP-4 per thread, uniform per-block A/W branch)
//   grid.y row in [0, 8192): row < 4096 -> A row b; else W row n = row - 4096.
//   Also zeroes g_cnt (runs before gemm1).
// ---------------------------------------------------------------------------
__global__ void pack_AW_kernel(const float* __restrict__ x_l4,
                               const float* __restrict__ x_l23,
                               const float* __restrict__ cue,
                               const float* __restrict__ task,
                               const float* __restrict__ x_prev,
                               const float* __restrict__ W_in,
                               const float* __restrict__ W_rec) {
    const int row = blockIdx.y;
    const int k0 = blockIdx.x * 1024 + threadIdx.x;
    if (row == 0 && k0 == 0) g_cnt = 0;
    if (row < B_DIM) {
        float v[4];
#pragma unroll
        for (int i = 0; i < 4; i++) {
            int k = k0 + i * 256;
            v[i] = (k < KACT) ? a_elem(row, k, x_l4, x_l23, cue, task, x_prev) : 0.0f;
        }
#pragma unroll
        for (int i = 0; i < 4; i++) {
            int k = k0 + i * 256;
            if (k < KP) g_A16[(size_t)row * KP + k] = __float2half_rn(v[i]);
        }
    } else {
        const int n = row - B_DIM;
        float v[4];
#pragma unroll
        for (int i = 0; i < 4; i++) {
            int k = k0 + i * 256;
            v[i] = (k < KACT) ? w_elem(n, k, W_in, W_rec) : 0.0f;
        }
#pragma unroll
        for (int i = 0; i < 4; i++) {
            int k = k0 + i * 256;
            if (k < KP) g_W16[(size_t)n * KP + k] = __float2half_rn(v[i]);
        }
    }
}

// W2 rows (mu | fb | pi | pad) -> fp16 hi/lo split + fp32 bias (MLP-4)
__global__ void pack_W2_kernel(const float* __restrict__ W_mu, const float* __restrict__ b_mu,
                               const float* __restrict__ W_fb, const float* __restrict__ b_fb,
                               const float* __restrict__ W_pi, const float* __restrict__ b_pi) {
    const int r = blockIdx.y;
    const int k0 = blockIdx.x * 1024 + threadIdx.x;
    const float* src = (r < N_DIM) ? (W_mu + (size_t)r * K2)
                     : (r < 2 * N_DIM) ? (W_fb + (size_t)(r - N_DIM) * K2)
                     : (r == 2 * N_DIM) ? W_pi : nullptr;
    float v[4];
#pragma unroll
    for (int i = 0; i < 4; i++) {
        int k = k0 + i * 256;
        v[i] = (src && k < K2) ? src[k] : 0.0f;
    }
#pragma unroll
    for (int i = 0; i < 4; i++) {
        int k = k0 + i * 256;
        if (k < K2) {
            __half hi = __float2half_rn(v[i]);
            __half lo = __float2half_rn(v[i] - __half2float(hi));
            g_W2h[(size_t)r * K2 + k] = hi;
            g_W2l[(size_t)r * K2 + k] = lo;
        }
    }
    if (k0 == 0) {
        float bb = 0.0f;
        if (r < N_DIM)           bb = b_mu[r];
        else if (r < 2 * N_DIM)  bb = b_fb[r - N_DIM];
        else if (r == 2 * N_DIM) bb = b_pi[0];
        g_b2[r] = bb;
    }
}

// ---------------------------------------------------------------------------
// Shared GEMM geometry: CTA 128x128, BK=64, 2-stage cp.async, 8 warps (2m x 4n)
// ---------------------------------------------------------------------------
#define BMt 128
#define BNt 128
#define STRIDE 144                       // bytes per smem row (128 data + 16 pad)
#define STAGE_BYTES (256 * STRIDE)       // 36864 (A: rows 0-127, B: rows 128-255)
#define STAGES 2
#define SMEM_DYN (STAGES * STAGE_BYTES)  // 73728

__device__ __forceinline__ void load_tile(uint32_t s, const __half* Abase, const __half* Bbase,
                                          size_t a_kstride, size_t b_kstride,
                                          int arow0, int brow0, size_t akoff, size_t bkoff,
                                          int tid) {
#pragma unroll
    for (int i = 0; i < 4; i++) {                     // A: 128 rows x 8 chunks
        int idx = tid + i * 256;
        int row = idx >> 3, ch = idx & 7;
        const char* g = (const char*)Abase
            + ((size_t)(arow0 + row) * a_kstride + akoff) * 2 + ch * 16;
        cp_async16(s + row * STRIDE + ch * 16, g);
    }
#pragma unroll
    for (int i = 0; i < 4; i++) {                     // B: 128 rows x 8 chunks
        int idx = tid + i * 256;
        int row = idx >> 3, ch = idx & 7;
        const char* g = (const char*)Bbase
            + ((size_t)(brow0 + row) * b_kstride + bkoff) * 2 + ch * 16;
        cp_async16(s + (128 + row) * STRIDE + ch * 16, g);
    }
}

// Compute one 64-wide k-tile from smem stage into acc
__device__ __forceinline__ void mma_tile(float (&acc)[4][4][4], uint32_t As, uint32_t Bs,
                                         int wm, int wn, int lrow, int lcol) {
#pragma unroll
    for (int ks = 0; ks < 4; ks++) {
        const uint32_t coff = (ks * 16 + lcol) * 2;
        uint32_t a[4][4];
#pragma unroll
        for (int mf = 0; mf < 4; mf++)
            ldm_x4(a[mf][0], a[mf][1], a[mf][2], a[mf][3],
                   As + (wm + mf * 16 + lrow) * STRIDE + coff);
        uint32_t b[2][4];
#pragma unroll
        for (int nt = 0; nt < 2; nt++)
            ldm_x4(b[nt][0], b[nt][1], b[nt][2], b[nt][3],
                   Bs + (wn + nt * 16 + lrow) * STRIDE + coff);
#pragma unroll
        for (int mf = 0; mf < 4; mf++)
#pragma unroll
            for (int nf = 0; nf < 4; nf++) {
                const int nt = nf >> 1, hi = nf & 1;
                mma_f16(acc[mf][nf][0], acc[mf][nf][1], acc[mf][nf][2], acc[mf][nf][3],
                        a[mf][0], a[mf][1], a[mf][2], a[mf][3],
                        b[nt][hi], b[nt][2 + hi]);
            }
    }
}

// ---------------------------------------------------------------------------
// GEMM 1 (mma.sync fp16): drive = A16 @ W16^T + b_in, fused spiking epilogue.
//   Epilogue also emits x as fp16 into g_x16 (stage-2 operand).
// ---------------------------------------------------------------------------
__global__ __launch_bounds__(256, 2)
void gemm1_mma(const float* __restrict__ v_prev, const float* __restrict__ z_prev,
               const float* __restrict__ x_prev, const float* __restrict__ b_prev,
               const float* __restrict__ adapt_mask, const float* __restrict__ b_in,
               float* __restrict__ out) {
    extern __shared__ __align__(256) char smem[];
    const uint32_t sb = smem_u32(smem);
    const int tid = threadIdx.x, wid = tid >> 5, lane = tid & 31;
    const int bn = blockIdx.x, bm = blockIdx.y;
    const int wm = (wid & 1) * 64;
    const int wn = (wid >> 1) * 32;
    const int lrow = lane & 15;
    const int lcol = ((lane >> 4) & 1) * 8;

    float acc[4][4][4];
#pragma unroll
    for (int i = 0; i < 4; i++)
#pragma unroll
        for (int j = 0; j < 4; j++)
#pragma unroll
            for (int q = 0; q < 4; q++) acc[i][j][q] = 0.0f;

    load_tile(sb, g_A16, g_W16, KP, KP, bm * BMt, bn * BNt, 0, 0, tid);
    CP_COMMIT();

    for (int t = 0; t < NT_G1; t++) {
        if (t + 1 < NT_G1) {
            load_tile(sb + ((t + 1) & 1) * STAGE_BYTES, g_A16, g_W16, KP, KP,
                      bm * BMt, bn * BNt, (size_t)(t + 1) * BKt, (size_t)(t + 1) * BKt, tid);
            CP_COMMIT();
            CP_WAIT1();
        } else {
            CP_WAIT0();
        }
        __syncthreads();
        const uint32_t As = sb + (t & 1) * STAGE_BYTES;
        mma_tile(acc, As, As + 128 * STRIDE, wm, wn, lrow, lcol);
        __syncthreads();
    }

    // --- fused spiking epilogue from fragments ---
    const int grow0 = bm * BMt + wm + (lane >> 2);
    const int gcol0 = bn * BNt + wn + (lane & 3) * 2;
#pragma unroll
    for (int mf = 0; mf < 4; mf++) {
#pragma unroll
        for (int h = 0; h < 2; h++) {
            const int row = grow0 + mf * 16 + h * 8;
#pragma unroll
            for (int nf = 0; nf < 4; nf++) {
                const int col = gcol0 + nf * 8;
                const size_t o = (size_t)row * NV2 + col;
                float2 bi = *(const float2*)(b_in + col);
                float2 am = *(const float2*)(adapt_mask + col);
                float2 vp = *(const float2*)(v_prev + o);
                float2 zp = *(const float2*)(z_prev + o);
                float2 bp = *(const float2*)(b_prev + o);
                float2 xp = *(const float2*)(x_prev + o);
                float d[2] = { acc[mf][nf][h * 2 + 0], acc[mf][nf][h * 2 + 1] };
                float vo[2], zo[2], xo[2], bo[2];
#pragma unroll
                for (int j = 0; j < 2; j++) {
                    float drive = d[j] + ((const float*)&bi)[j];
                    float v = BETA_MEM * ((const float*)&vp)[j] + drive - ((const float*)&zp)[j];
                    float Bth = fmaf(BETA_AD, ((const float*)&bp)[j], 1.0f);
                    float u = v - Bth;
                    float z = u > 0.0f ? 1.0f : 0.0f;
                    if (fabsf(u) < TAU_BORDER) {
                        int idx = atomicAdd(&g_cnt, 1);
                        if (idx < MAXB) g_list[idx] = make_int2(row, col + j);
                    }
                    vo[j] = v; zo[j] = z;
                    bo[j] = (RHO_AD * ((const float*)&bp)[j] + ONE_M_RHO * z) * ((const float*)&am)[j];
                    xo[j] = ALPHA_F * ((const float*)&xp)[j] + z;
                }
                *(float2*)(out + OFF_V + o) = make_float2(vo[0], vo[1]);
                *(float2*)(out + OFF_Z + o) = make_float2(zo[0], zo[1]);
                *(float2*)(out + OFF_X + o) = make_float2(xo[0], xo[1]);
                *(float2*)(out + OFF_B + o) = make_float2(bo[0], bo[1]);
                *(__half2*)(g_x16 + o) = __floats2half2_rn(xo[0], xo[1]);
            }
        }
    }
}

// ---------------------------------------------------------------------------
// GEMM 2 (mma.sync fp16, 2-term W-split): logits = x @ (W2h + W2l)^T + b2
// ---------------------------------------------------------------------------
__global__ __launch_bounds__(256, 2)
void gemm2_mma(float* __restrict__ out) {
    extern __shared__ __align__(256) char smem[];
    const uint32_t sb = smem_u32(smem);
    const int tid = threadIdx.x, wid = tid >> 5, lane = tid & 31;
    const int bn = blockIdx.x, bm = blockIdx.y;
    const int wm = (wid & 1) * 64;
    const int wn = (wid >> 1) * 32;
    const int lrow = lane & 15;
    const int lcol = ((lane >> 4) & 1) * 8;

    float acc[4][4][4];
#pragma unroll
    for (int i = 0; i < 4; i++)
#pragma unroll
        for (int j = 0; j < 4; j++)
#pragma unroll
            for (int q = 0; q < 4; q++) acc[i][j][q] = 0.0f;

    load_tile(sb, g_x16, g_W2h, K2, K2, bm * BMt, bn * BNt, 0, 0, tid);
    CP_COMMIT();

    for (int t = 0; t < NT_G2; t++) {
        if (t + 1 < NT_G2) {
            const int tn = t + 1;
            const __half* Wb = (tn >> 6) ? g_W2l : g_W2h;
            load_tile(sb + (tn & 1) * STAGE_BYTES, g_x16, Wb, K2, K2,
                      bm * BMt, bn * BNt,
                      (size_t)(tn & 63) * BKt, (size_t)(tn & 63) * BKt, tid);
            CP_COMMIT();
            CP_WAIT1();
        } else {
            CP_WAIT0();
        }
        __syncthreads();
        const uint32_t As = sb + (t & 1) * STAGE_BYTES;
        mma_tile(acc, As, As + 128 * STRIDE, wm, wn, lrow, lcol);
        __syncthreads();
    }

    // --- scatter epilogue ---
    const int grow0 = bm * BMt + wm + (lane >> 2);
    const int gcol0 = bn * BNt + wn + (lane & 3) * 2;
#pragma unroll
    for (int mf = 0; mf < 4; mf++) {
#pragma unroll
        for (int h = 0; h < 2; h++) {
            const int r = grow0 + mf * 16 + h * 8;
#pragma unroll
            for (int nf = 0; nf < 4; nf++) {
                const int col = gcol0 + nf * 8;
#pragma unroll
                for (int j = 0; j < 2; j++) {
                    const int c = col + j;
                    float val = acc[mf][nf][h * 2 + j] + g_b2[c];
                    if (c < N_DIM) {
                        out[OFF_MU + (size_t)r * N_DIM + c] = val;
                    } else if (c < 2 * N_DIM) {
                        out[OFF_FB + (size_t)r * N_DIM + (c - N_DIM)] = val;
                    } else if (c == 2 * N_DIM) {
                        float sp = fmaxf(val, 0.0f) + log1pf(expf(-fabsf(val)));
                        out[OFF_PI + r] = fminf(sp, 10.0f);
                    }
                }
            }
        }
    }
}

// ---------------------------------------------------------------------------
// Borderline refinement (block-per-item): one 256-thread block per flagged
// element. All k-loads issued in parallel (each thread ~18 strided k's),
// then shuffle+smem double reduction. Overwrites v, z, x, b; patches g_x16.
// ---------------------------------------------------------------------------
__global__ __launch_bounds__(256)
void refine_kernel(const float* __restrict__ x_l4, const float* __restrict__ x_l23,
                   const float* __restrict__ cue, const float* __restrict__ task,
                   const float* __restrict__ v_prev, const float* __restrict__ z_prev,
                   const float* __restrict__ x_prev, const float* __restrict__ b_prev,
                   const float* __restrict__ adapt_mask,
                   const float* __restrict__ W_in, const float* __restrict__ b_in,
                   const float* __restrict__ W_rec,
                   float* __restrict__ out) {
    __shared__ double red[8];
    const int tid = threadIdx.x, lane = tid & 31, wid = tid >> 5;
    int nitems = g_cnt < MAXB ? g_cnt : MAXB;

    for (int i = blockIdx.x; i < nitems; i += gridDim.x) {
        int2 rc = g_list[i];
        double s = 0.0;
        for (int k = tid; k < KACT; k += 256) {
            float a = a_elem(rc.x, k, x_l4, x_l23, cue, task, x_prev);
            float w = w_elem(rc.y, k, W_in, W_rec);
            s += (double)a * (double)w;
        }
#pragma unroll
        for (int o = 16; o > 0; o >>= 1)
            s += __shfl_xor_sync(0xffffffffu, s, o);
        if (lane == 0) red[wid] = s;
        __syncthreads();
        if (wid == 0) {
            double t = (lane < 8) ? red[lane] : 0.0;
#pragma unroll
            for (int o = 4; o > 0; o >>= 1)
                t += __shfl_xor_sync(0xffffffffu, t, o);
            if (lane == 0) {
                size_t idx = (size_t)rc.x * NV2 + rc.y;
                double drive = t + (double)b_in[rc.y];
                double vd = (double)BETA_MEM * (double)v_prev[idx] + drive
                            - (double)z_prev[idx];
                float bp = b_prev[idx];
                float Bth = fmaf(BETA_AD, bp, 1.0f);
                float z = (vd - (double)Bth) > 0.0 ? 1.0f : 0.0f;
                float xn = ALPHA_F * x_prev[idx] + z;
                out[OFF_V + idx] = (float)vd;
                out[OFF_Z + idx] = z;
                out[OFF_X + idx] = xn;
                out[OFF_B + idx] = (RHO_AD * bp + ONE_M_RHO * z) * adapt_mask[rc.y];
                g_x16[idx] = __float2half_rn(xn);
            }
        }
        __syncthreads();   // red[] reused next item
    }
}

// ---------------------------------------------------------------------------
// Softmax over [B, 180] in place (one warp per row)
// ---------------------------------------------------------------------------
__global__ void softmax_kernel(float* __restrict__ out) {
    int warp = (blockIdx.x * blockDim.x + threadIdx.x) >> 5;
    int lane = threadIdx.x & 31;
    if (warp >= B_DIM) return;
    float* row = out + OFF_MU + (size_t)warp * N_DIM;

    float vals[6];
    float mx = -1e30f;
#pragma unroll
    for (int t = 0; t < 6; t++) {
        int j = lane + t * 32;
        vals[t] = (j < N_DIM) ? row[j] : -1e30f;
        mx = fmaxf(mx, vals[t]);
    }
#pragma unroll
    for (int o = 16; o > 0; o >>= 1) mx = fmaxf(mx, __shfl_xor_sync(0xffffffffu, mx, o));
    float s = 0.0f;
#pragma unroll
    for (int t = 0; t < 6; t++) {
        int j = lane + t * 32;
        float e = expf(vals[t] - mx);
        vals[t] = e;
        if (j < N_DIM) s += e;
    }
#pragma unroll
    for (int o = 16; o > 0; o >>= 1) s += __shfl_xor_sync(0xffffffffu, s, o);
    float inv = 1.0f / s;
#pragma unroll
    for (int t = 0; t < 6; t++) {
        int j = lane + t * 32;
        if (j < N_DIM) row[j] = vals[t] * inv;
    }
}

// ---------------------------------------------------------------------------
// Launch (capture slot #4 = refine_kernel -- verifies this round's fix)
// ---------------------------------------------------------------------------
extern "C" void kernel_launch(void* const* d_in, const int* in_sizes, int n_in,
                              void* d_out, int out_size) {
    const float* x_l4   = (const float*)d_in[0];
    const float* x_l23  = (const float*)d_in[1];
    const float* cue    = (const float*)d_in[2];
    const float* task   = (const float*)d_in[3];
    const float* v_prev = (const float*)d_in[4];
    const float* z_prev = (const float*)d_in[5];
    const float* x_prev = (const float*)d_in[6];
    const float* b_prev = (const float*)d_in[7];
    const float* amask  = (const float*)d_in[8];
    const float* W_in   = (const float*)d_in[9];
    const float* b_in   = (const float*)d_in[10];
    const float* W_rec  = (const float*)d_in[11];
    const float* W_mu   = (const float*)d_in[12];
    const float* b_mu   = (const float*)d_in[13];
    const float* W_fb   = (const float*)d_in[14];
    const float* b_fb   = (const float*)d_in[15];
    const float* W_pi   = (const float*)d_in[16];
    const float* b_pi   = (const float*)d_in[17];
    float* out = (float*)d_out;

    cudaFuncSetAttribute(gemm1_mma, cudaFuncAttributeMaxDynamicSharedMemorySize, SMEM_DYN);
    cudaFuncSetAttribute(gemm2_mma, cudaFuncAttributeMaxDynamicSharedMemorySize, SMEM_DYN);

    pack_AW_kernel<<<dim3((KP + 1023) / 1024, 2 * B_DIM), 256>>>(
        x_l4, x_l23, cue, task, x_prev, W_in, W_rec);                       // 1
    pack_W2_kernel<<<dim3((K2 + 1023) / 1024, N2PAD), 256>>>(
        W_mu, b_mu, W_fb, b_fb, W_pi, b_pi);                                // 2
    gemm1_mma<<<dim3(NV2 / BNt, B_DIM / BMt), 256, SMEM_DYN>>>(
        v_prev, z_prev, x_prev, b_prev, amask, b_in, out);                  // 3
    refine_kernel<<<2048, 256>>>(x_l4, x_l23, cue, task, v_prev, z_prev,
                                 x_prev, b_prev, amask, W_in, b_in, W_rec, out); // 4 (profiled)
    gemm2_mma<<<dim3(N2PAD / BNt, B_DIM / BMt), 256, SMEM_DYN>>>(out);      // 5
    softmax_kernel<<<(B_DIM * 32 + 255) / 256, 256>>>(out);                 // 6
}